// round 11
// baseline (speedup 1.0000x reference)
#include <cuda_runtime.h>
#include <cuda_bf16.h>
#include <cstdint>

// Problem constants
#define B_ROWS 4096
#define NDOM 8
#define D0 1024
#define D1 1024
#define D2 512
#define D3 256
#define MAXT64 72
#define MTILE 64

// ---------------- device scratch ----------------
__device__ int   g_perm[B_ROWS];
__device__ int   g_off[NDOM + 1];
__device__ int   g_tile_d64[MAXT64];
__device__ int   g_tile_m64[MAXT64];
__device__ int   g_nt64;
__device__ float g_h1[B_ROWS * D1];
__device__ float g_h2[B_ROWS * D2];

#define MMA_BF16(d, a, b0, b1)                                                \
    asm volatile(                                                             \
        "mma.sync.aligned.m16n8k16.row.col.f32.bf16.bf16.f32 "                \
        "{%0,%1,%2,%3}, {%4,%5,%6,%7}, {%8,%9}, {%0,%1,%2,%3};"               \
        : "+f"((d)[0]), "+f"((d)[1]), "+f"((d)[2]), "+f"((d)[3])              \
        : "r"((a)[0]), "r"((a)[1]), "r"((a)[2]), "r"((a)[3]),                 \
          "r"(b0), "r"(b1))

#define LDSM_X4(r, addr)                                                      \
    asm volatile("ldmatrix.sync.aligned.m8n8.x4.shared.b16 "                  \
                 "{%0,%1,%2,%3}, [%4];"                                       \
                 : "=r"((r)[0]), "=r"((r)[1]), "=r"((r)[2]), "=r"((r)[3])     \
                 : "r"(addr))

#define LDSM_X4T(r0, r1, r2, r3, addr)                                        \
    asm volatile("ldmatrix.sync.aligned.m8n8.x4.trans.shared.b16 "            \
                 "{%0,%1,%2,%3}, [%4];"                                       \
                 : "=r"(r0), "=r"(r1), "=r"(r2), "=r"(r3)                     \
                 : "r"(addr))

__device__ __forceinline__ void split_store(char* pHi, char* pLo, float4 v) {
    __nv_bfloat162 h01 = __floats2bfloat162_rn(v.x, v.y);
    __nv_bfloat162 h23 = __floats2bfloat162_rn(v.z, v.w);
    float2 f01 = __bfloat1622float2(h01);
    float2 f23 = __bfloat1622float2(h23);
    __nv_bfloat162 l01 = __floats2bfloat162_rn(v.x - f01.x, v.y - f01.y);
    __nv_bfloat162 l23 = __floats2bfloat162_rn(v.z - f23.x, v.w - f23.y);
    uint2 hv, lv;
    hv.x = *(uint32_t*)&h01; hv.y = *(uint32_t*)&h23;
    lv.x = *(uint32_t*)&l01; lv.y = *(uint32_t*)&l23;
    *(uint2*)pHi = hv;
    *(uint2*)pLo = lv;
}

// ---------------- permutation + tile list ----------------
__global__ void build_perm(const int* __restrict__ ind) {
    __shared__ int cnt[NDOM];
    __shared__ int cur[NDOM];
    int t = threadIdx.x;
    if (t < NDOM) cnt[t] = 0;
    __syncthreads();
    for (int i = t; i < B_ROWS; i += blockDim.x) atomicAdd(&cnt[ind[i]], 1);
    __syncthreads();
    if (t == 0) {
        int s = 0;
        for (int d = 0; d < NDOM; d++) { g_off[d] = s; cur[d] = s; s += cnt[d]; }
        g_off[NDOM] = s;
        int n64 = 0;
        for (int d = 0; d < NDOM; d++) {
            int len = g_off[d + 1] - g_off[d];
            for (int m0 = 0; m0 < len; m0 += MTILE) {
                g_tile_d64[n64] = d; g_tile_m64[n64] = m0; n64++;
            }
        }
        g_nt64 = n64;
    }
    __syncthreads();
    for (int i = t; i < B_ROWS; i += blockDim.x) {
        int d = ind[i];
        int p = atomicAdd(&cur[d], 1);
        g_perm[p] = i;
    }
}

// ---------------- smem layout (bytes) ----------------
// A: [buf][split][row<64] rows of 32 bf16 (64B data, 80B stride)
// B: [buf][split][k<32]   rows of 128 bf16 (256B data, 272B stride)
#define ABYTES (4 * MTILE * 80)           // 20480
#define BBYTES (4 * 32 * 272)             // 34816
#define SM_RI  (ABYTES + BBYTES)
#define SM_BI  (SM_RI + MTILE * 4)
#define GEMM_SMEM (SM_BI + 512)           // ~56 KB -> 2 CTAs/SM

// ---------------- bf16 split (3-product) grouped GEMM ----------------
// Block tile 64 x 128, K-chunk 32, double-buffered, 256 threads / 8 warps
// (2M x 4N), warp tile 32 x 32. Fragments via ldmatrix. 2 CTAs per SM.
// MMA emission is product-major: 8 independent MMAs between acc reuse.
template <int LAYER>
__global__ __launch_bounds__(256, 2)
void gemm_mma(const float* __restrict__ xin, const float* __restrict__ sk,
              const float* __restrict__ dkk, const float* __restrict__ sb,
              const float* __restrict__ db, float* __restrict__ outp) {
    constexpr int K = (LAYER == 0) ? D0 : (LAYER == 1) ? D1 : D2;
    constexpr int N = (LAYER == 0) ? D1 : (LAYER == 1) ? D2 : D3;
    constexpr int NCH = K / 32;
    constexpr int MT_W = MTILE / 32;     // 2 m16 tiles per warp
    constexpr int AIT = MTILE / 32;      // 2 A loader items per thread

    const int tyb = blockIdx.y;
    if (tyb >= g_nt64) return;
    const int d   = g_tile_d64[tyb];
    const int m0  = g_tile_m64[tyb];
    const int off = g_off[d];
    const int len = g_off[d + 1] - off;
    const int n0  = blockIdx.x * 128;

    extern __shared__ char smc[];
    int*   rowIdx = (int*)(smc + SM_RI);
    float* biasS  = (float*)(smc + SM_BI);

    const int tid  = threadIdx.x;
    const int lane = tid & 31;
    const int w    = tid >> 5;
    const int mw   = w >> 2;
    const int nw   = w & 3;
    const int grp  = lane >> 2;
    const int tig  = lane & 3;

    if (tid < MTILE) {
        int r = m0 + tid;
        int row = -1;
        if (r < len) row = (LAYER == 0) ? g_perm[off + r] : (off + r);
        rowIdx[tid] = row;
    }
    if (tid >= 128 && tid < 160) {
        int q = tid - 128;
        float4 a = *(const float4*)(sb + n0 + q * 4);
        float4 b = *(const float4*)(db + (size_t)d * N + n0 + q * 4);
        a.x += b.x; a.y += b.y; a.z += b.z; a.w += b.w;
        *(float4*)(biasS + q * 4) = a;
    }
    __syncthreads();

    const float* Ap  = (LAYER == 0) ? xin : (LAYER == 1) ? g_h1 : g_h2;
    float*       Cp  = (LAYER == 0) ? g_h1 : (LAYER == 1) ? g_h2 : outp;
    const float* dkd = dkk + (size_t)d * K * N;

    float acc[MT_W][4][4];
#pragma unroll
    for (int i = 0; i < MT_W; i++)
#pragma unroll
        for (int j = 0; j < 4; j++)
#pragma unroll
            for (int q = 0; q < 4; q++) acc[i][j][q] = 0.f;

    // loader coords
    const int ldr = tid >> 3;
    const int fq  = tid & 7;
    int rws[AIT];
#pragma unroll
    for (int i = 0; i < AIT; i++) rws[i] = rowIdx[ldr + 32 * i];

    // fragment read addresses (u32 shared space)
    const uint32_t ubase = (uint32_t)__cvta_generic_to_shared(smc);
    const int Lrow = (lane & 7) + ((lane >> 3) & 1) * 8;
    const int Lk16 = (lane >> 4) & 1;
    const uint32_t aBase = ubase +
        (uint32_t)((mw * (MTILE / 2) + Lrow) * 80 + Lk16 * 16);
    const int bm = lane >> 3;
    const int bk = (bm & 1) * 8 + (lane & 7);
    const int bn = nw * 32 + (bm >> 1) * 8;
    const uint32_t bBase = ubase + (uint32_t)ABYTES +
        (uint32_t)(bk * 272 + bn * 2);

    float4 avA[AIT], avW[4];

#define LOADC(c)                                                              \
    {                                                                         \
        const int k0 = (c) * 32;                                              \
        _Pragma("unroll")                                                     \
        for (int i = 0; i < AIT; i++) {                                       \
            int rr = rws[i];                                                  \
            avA[i] = (rr >= 0)                                                \
                ? *(const float4*)(Ap + (size_t)rr * K + k0 + fq * 4)         \
                : make_float4(0.f, 0.f, 0.f, 0.f);                            \
        }                                                                     \
        _Pragma("unroll")                                                     \
        for (int i = 0; i < 4; i++) {                                         \
            int co = n0 + (fq + 8 * i) * 4;                                   \
            float4 s = *(const float4*)(sk  + (size_t)(k0 + ldr) * N + co);   \
            float4 t = *(const float4*)(dkd + (size_t)(k0 + ldr) * N + co);   \
            avW[i].x = s.x * t.x; avW[i].y = s.y * t.y;                       \
            avW[i].z = s.z * t.z; avW[i].w = s.w * t.w;                       \
        }                                                                     \
    }

#define STOREC(c)                                                             \
    {                                                                         \
        const int buf = (c) & 1;                                              \
        _Pragma("unroll")                                                     \
        for (int i = 0; i < AIT; i++) {                                       \
            int row = ldr + 32 * i;                                           \
            char* ph = smc + (buf * 2 + 0) * (MTILE * 80) + row * 80 + fq * 8;\
            char* pl = smc + (buf * 2 + 1) * (MTILE * 80) + row * 80 + fq * 8;\
            split_store(ph, pl, avA[i]);                                      \
        }                                                                     \
        _Pragma("unroll")                                                     \
        for (int i = 0; i < 4; i++) {                                         \
            char* ph = smc + ABYTES + (buf * 2 + 0) * 8704 +                  \
                       ldr * 272 + (fq + 8 * i) * 8;                          \
            char* pl = smc + ABYTES + (buf * 2 + 1) * 8704 +                  \
                       ldr * 272 + (fq + 8 * i) * 8;                          \
            split_store(ph, pl, avW[i]);                                      \
        }                                                                     \
    }

    LOADC(0);
    STOREC(0);

    for (int c = 0; c < NCH; c++) {
        const int buf = c & 1;
        __syncthreads();
        if (c + 1 < NCH) LOADC(c + 1);

        const uint32_t aHi = aBase + (uint32_t)((buf * 2 + 0) * (MTILE * 80));
        const uint32_t aLo = aBase + (uint32_t)((buf * 2 + 1) * (MTILE * 80));
        const uint32_t bHi = bBase + (uint32_t)((buf * 2 + 0) * 8704);
        const uint32_t bLo = bBase + (uint32_t)((buf * 2 + 1) * 8704);
#pragma unroll
        for (int ks = 0; ks < 2; ks++) {
            uint32_t ah[MT_W][4], al[MT_W][4];
#pragma unroll
            for (int mt = 0; mt < MT_W; mt++) {
                LDSM_X4(ah[mt], aHi + mt * (16 * 80) + ks * 32);
                LDSM_X4(al[mt], aLo + mt * (16 * 80) + ks * 32);
            }
            uint32_t bh[4][2], bl[4][2];
#pragma unroll
            for (int np = 0; np < 2; np++) {
                LDSM_X4T(bh[2 * np][0], bh[2 * np][1],
                         bh[2 * np + 1][0], bh[2 * np + 1][1],
                         bHi + ks * (16 * 272) + np * 32);
                LDSM_X4T(bl[2 * np][0], bl[2 * np][1],
                         bl[2 * np + 1][0], bl[2 * np + 1][1],
                         bLo + ks * (16 * 272) + np * 32);
            }
            // product-major passes: 8 independent MMAs between acc reuse
#pragma unroll
            for (int nt = 0; nt < 4; nt++)
#pragma unroll
                for (int mt = 0; mt < MT_W; mt++)
                    MMA_BF16(acc[mt][nt], ah[mt], bh[nt][0], bh[nt][1]);
#pragma unroll
            for (int nt = 0; nt < 4; nt++)
#pragma unroll
                for (int mt = 0; mt < MT_W; mt++)
                    MMA_BF16(acc[mt][nt], ah[mt], bl[nt][0], bl[nt][1]);
#pragma unroll
            for (int nt = 0; nt < 4; nt++)
#pragma unroll
                for (int mt = 0; mt < MT_W; mt++)
                    MMA_BF16(acc[mt][nt], al[mt], bh[nt][0], bh[nt][1]);
        }
        if (c + 1 < NCH) STOREC(c + 1);
    }

    // ---------------- epilogue: bias + relu + (scatter) store ----------------
#pragma unroll
    for (int mt = 0; mt < MT_W; mt++) {
#pragma unroll
        for (int half = 0; half < 2; half++) {
            int mrow = mw * (MTILE / 2) + mt * 16 + grp + half * 8;
            int r = m0 + mrow;
            if (r < len) {
                int orow = (LAYER == 2) ? g_perm[off + r] : (off + r);
                float* crow = Cp + (size_t)orow * N + n0;
#pragma unroll
                for (int nt = 0; nt < 4; nt++) {
                    int col = nw * 32 + nt * 8 + 2 * tig;
                    float2 o;
                    o.x = fmaxf(acc[mt][nt][half * 2 + 0] + biasS[col], 0.f);
                    o.y = fmaxf(acc[mt][nt][half * 2 + 1] + biasS[col + 1], 0.f);
                    *(float2*)(crow + col) = o;
                }
            }
        }
    }
}

// ---------------- launch ----------------
extern "C" void kernel_launch(void* const* d_in, const int* in_sizes, int n_in,
                              void* d_out, int out_size) {
    const float* x   = (const float*)d_in[0];
    const int*   ind = (const int*)  d_in[1];
    const float* sk0 = (const float*)d_in[2];
    const float* sb0 = (const float*)d_in[3];
    const float* dk0 = (const float*)d_in[4];
    const float* db0 = (const float*)d_in[5];
    const float* sk1 = (const float*)d_in[6];
    const float* sb1 = (const float*)d_in[7];
    const float* dk1 = (const float*)d_in[8];
    const float* db1 = (const float*)d_in[9];
    const float* sk2 = (const float*)d_in[10];
    const float* sb2 = (const float*)d_in[11];
    const float* dk2 = (const float*)d_in[12];
    const float* db2 = (const float*)d_in[13];
    float* out = (float*)d_out;

    cudaFuncSetAttribute(gemm_mma<0>, cudaFuncAttributeMaxDynamicSharedMemorySize, GEMM_SMEM);
    cudaFuncSetAttribute(gemm_mma<1>, cudaFuncAttributeMaxDynamicSharedMemorySize, GEMM_SMEM);
    cudaFuncSetAttribute(gemm_mma<2>, cudaFuncAttributeMaxDynamicSharedMemorySize, GEMM_SMEM);

    build_perm<<<1, 256>>>(ind);

    gemm_mma<0><<<dim3(D1 / 128, MAXT64), 256, GEMM_SMEM>>>(x, sk0, dk0, sb0, db0, nullptr);
    gemm_mma<1><<<dim3(D2 / 128, MAXT64), 256, GEMM_SMEM>>>(nullptr, sk1, dk1, sb1, db1, nullptr);
    gemm_mma<2><<<dim3(D3 / 128, MAXT64), 256, GEMM_SMEM>>>(nullptr, sk2, dk2, sb2, db2, out);
}

// round 12
// speedup vs baseline: 1.0545x; 1.0545x over previous
#include <cuda_runtime.h>
#include <cuda_bf16.h>
#include <cstdint>

// Problem constants
#define B_ROWS 4096
#define NDOM 8
#define D0 1024
#define D1 1024
#define D2 512
#define D3 256
#define MAXT64 72
#define MTILE 64
#define STAGES 3
#define PADR 64

// ---------------- device scratch ----------------
__device__ int   g_perm[B_ROWS];
__device__ int   g_off[NDOM + 1];
__device__ int   g_tile_d64[MAXT64];
__device__ int   g_tile_m64[MAXT64];
__device__ int   g_nt64;
// bf16 hi/lo planes: activations (sorted order) and fused weights [d][k][n]
__device__ __nv_bfloat16 g_xh[(B_ROWS + PADR) * D0];
__device__ __nv_bfloat16 g_xl[(B_ROWS + PADR) * D0];
__device__ __nv_bfloat16 g_h1h[(B_ROWS + PADR) * D1];
__device__ __nv_bfloat16 g_h1l[(B_ROWS + PADR) * D1];
__device__ __nv_bfloat16 g_h2h[(B_ROWS + PADR) * D2];
__device__ __nv_bfloat16 g_h2l[(B_ROWS + PADR) * D2];
__device__ __nv_bfloat16 g_w0h[NDOM * D0 * D1];
__device__ __nv_bfloat16 g_w0l[NDOM * D0 * D1];
__device__ __nv_bfloat16 g_w1h[NDOM * D1 * D2];
__device__ __nv_bfloat16 g_w1l[NDOM * D1 * D2];
__device__ __nv_bfloat16 g_w2h[NDOM * D2 * D3];
__device__ __nv_bfloat16 g_w2l[NDOM * D2 * D3];

#define MMA_BF16(d, a, b0, b1)                                                \
    asm volatile(                                                             \
        "mma.sync.aligned.m16n8k16.row.col.f32.bf16.bf16.f32 "                \
        "{%0,%1,%2,%3}, {%4,%5,%6,%7}, {%8,%9}, {%0,%1,%2,%3};"               \
        : "+f"((d)[0]), "+f"((d)[1]), "+f"((d)[2]), "+f"((d)[3])              \
        : "r"((a)[0]), "r"((a)[1]), "r"((a)[2]), "r"((a)[3]),                 \
          "r"(b0), "r"(b1))

#define LDSM_X4(r, addr)                                                      \
    asm volatile("ldmatrix.sync.aligned.m8n8.x4.shared.b16 "                  \
                 "{%0,%1,%2,%3}, [%4];"                                       \
                 : "=r"((r)[0]), "=r"((r)[1]), "=r"((r)[2]), "=r"((r)[3])     \
                 : "r"(addr))

#define LDSM_X4T(r0, r1, r2, r3, addr)                                        \
    asm volatile("ldmatrix.sync.aligned.m8n8.x4.trans.shared.b16 "            \
                 "{%0,%1,%2,%3}, [%4];"                                       \
                 : "=r"(r0), "=r"(r1), "=r"(r2), "=r"(r3)                     \
                 : "r"(addr))

#define CP16(dst, src)                                                        \
    asm volatile("cp.async.cg.shared.global [%0], [%1], 16;"                  \
                 :: "r"(dst), "l"(src))
#define CP_COMMIT() asm volatile("cp.async.commit_group;" ::: "memory")
#define CP_WAIT1()  asm volatile("cp.async.wait_group 1;" ::: "memory")

// split fp32 pair -> bf16 hi/lo packed words
__device__ __forceinline__ void split2(float x, float y,
                                       uint32_t& hi, uint32_t& lo) {
    __nv_bfloat162 h = __floats2bfloat162_rn(x, y);
    float2 f = __bfloat1622float2(h);
    __nv_bfloat162 l = __floats2bfloat162_rn(x - f.x, y - f.y);
    hi = *(uint32_t*)&h;
    lo = *(uint32_t*)&l;
}

// ---------------- permutation + tile list ----------------
__global__ void build_perm(const int* __restrict__ ind) {
    __shared__ int cnt[NDOM];
    __shared__ int cur[NDOM];
    int t = threadIdx.x;
    if (t < NDOM) cnt[t] = 0;
    __syncthreads();
    for (int i = t; i < B_ROWS; i += blockDim.x) atomicAdd(&cnt[ind[i]], 1);
    __syncthreads();
    if (t == 0) {
        int s = 0;
        for (int d = 0; d < NDOM; d++) { g_off[d] = s; cur[d] = s; s += cnt[d]; }
        g_off[NDOM] = s;
        int n64 = 0;
        for (int d = 0; d < NDOM; d++) {
            int len = g_off[d + 1] - g_off[d];
            for (int m0 = 0; m0 < len; m0 += MTILE) {
                g_tile_d64[n64] = d; g_tile_m64[n64] = m0; n64++;
            }
        }
        g_nt64 = n64;
    }
    __syncthreads();
    for (int i = t; i < B_ROWS; i += blockDim.x) {
        int d = ind[i];
        int p = atomicAdd(&cur[d], 1);
        g_perm[p] = i;
    }
}

// ---------------- prepass: gather + split x into sorted bf16 planes --------
__global__ void prep_x(const float* __restrict__ x) {
    int i = blockIdx.x * 256 + threadIdx.x;       // one float4
    if (i >= B_ROWS * D0 / 4) return;
    int row = i / (D0 / 4);
    int c4  = (i % (D0 / 4)) * 4;
    int prow = g_perm[row];
    float4 v = *(const float4*)(x + (size_t)prow * D0 + c4);
    uint32_t h0, l0, h1, l1;
    split2(v.x, v.y, h0, l0);
    split2(v.z, v.w, h1, l1);
    uint2 hv = make_uint2(h0, h1), lv = make_uint2(l0, l1);
    *(uint2*)(g_xh + (size_t)row * D0 + c4) = hv;
    *(uint2*)(g_xl + (size_t)row * D0 + c4) = lv;
}

// ---------------- prepass: fuse sk*dk, split to bf16 planes ----------------
template <int LAYER>
__global__ void prep_w(const float* __restrict__ sk, const float* __restrict__ dk) {
    constexpr int K = (LAYER == 0) ? D0 : (LAYER == 1) ? D1 : D2;
    constexpr int N = (LAYER == 0) ? D1 : (LAYER == 1) ? D2 : D3;
    __nv_bfloat16* wh = (LAYER == 0) ? g_w0h : (LAYER == 1) ? g_w1h : g_w2h;
    __nv_bfloat16* wl = (LAYER == 0) ? g_w0l : (LAYER == 1) ? g_w1l : g_w2l;
    int i = blockIdx.x * 256 + threadIdx.x;
    if (i >= NDOM * K * N / 4) return;
    int idx = i * 4;
    int kn  = idx % (K * N);
    float4 s = *(const float4*)(sk + kn);
    float4 t = *(const float4*)(dk + idx);
    float4 w;
    w.x = s.x * t.x; w.y = s.y * t.y; w.z = s.z * t.z; w.w = s.w * t.w;
    uint32_t h0, l0, h1, l1;
    split2(w.x, w.y, h0, l0);
    split2(w.z, w.w, h1, l1);
    *(uint2*)(wh + idx) = make_uint2(h0, h1);
    *(uint2*)(wl + idx) = make_uint2(l0, l1);
}

// ---------------- smem stage layout (bytes) ----------------
// aHi: 64 rows x 64B @80B stride (5120) | aLo +5120
// bHi: 32 rows x 256B @272B stride (8704) @10240 | bLo @18944
#define STAGEB 27648
#define GEMM_SMEM (STAGES * STAGEB + 512)   // ~83.5 KB -> 2 CTAs/SM

// ---------------- bf16 split (3-product) grouped GEMM, cp.async loader -----
// Block tile 64 x 128, K-chunk 32, 3-stage cp.async pipeline, 256 threads /
// 8 warps (2M x 4N), warp tile 32 x 32.
template <int LAYER>
__global__ __launch_bounds__(256, 2)
void gemm_mma(const float* __restrict__ sb, const float* __restrict__ db,
              float* __restrict__ outp) {
    constexpr int K = (LAYER == 0) ? D0 : (LAYER == 1) ? D1 : D2;
    constexpr int N = (LAYER == 0) ? D1 : (LAYER == 1) ? D2 : D3;
    constexpr int NCH = K / 32;
    constexpr int MT_W = MTILE / 32;

    const int tyb = blockIdx.y;
    if (tyb >= g_nt64) return;
    const int d   = g_tile_d64[tyb];
    const int m0  = g_tile_m64[tyb];
    const int off = g_off[d];
    const int len = g_off[d + 1] - off;
    const int n0  = blockIdx.x * 128;
    const int gmrow0 = off + m0;              // sorted-order global row base

    extern __shared__ char smc[];
    float* biasS = (float*)(smc + STAGES * STAGEB);

    const int tid  = threadIdx.x;
    const int lane = tid & 31;
    const int w    = tid >> 5;
    const int mw   = w >> 2;
    const int nw   = w & 3;
    const int grp  = lane >> 2;
    const int tig  = lane & 3;

    if (tid >= 128 && tid < 160) {
        int q = tid - 128;
        float4 a = *(const float4*)(sb + n0 + q * 4);
        float4 b = *(const float4*)(db + (size_t)d * N + n0 + q * 4);
        a.x += b.x; a.y += b.y; a.z += b.z; a.w += b.w;
        *(float4*)(biasS + q * 4) = a;
    }

    const __nv_bfloat16* Ah = (LAYER == 0) ? g_xh : (LAYER == 1) ? g_h1h : g_h2h;
    const __nv_bfloat16* Al = (LAYER == 0) ? g_xl : (LAYER == 1) ? g_h1l : g_h2l;
    const __nv_bfloat16* Wh = (LAYER == 0) ? g_w0h : (LAYER == 1) ? g_w1h : g_w2h;
    const __nv_bfloat16* Wl = (LAYER == 0) ? g_w0l : (LAYER == 1) ? g_w1l : g_w2l;
    __nv_bfloat16* Ch = (LAYER == 0) ? g_h1h : g_h2h;
    __nv_bfloat16* Cl = (LAYER == 0) ? g_h1l : g_h2l;

    const uint32_t ubase = (uint32_t)__cvta_generic_to_shared(smc);

    // copy coords
    const int arow = tid >> 2;            // 0..63
    const int aseg = (tid & 3) * 16;      // byte in 64B row
    const int brow = tid >> 4;            // 0..15 (+16 second pass)
    const int bseg = (tid & 15) * 16;     // byte in 256B row

    const char* aSrcH = (const char*)(Ah + (size_t)(gmrow0 + arow) * K) + aseg;
    const char* aSrcL = (const char*)(Al + (size_t)(gmrow0 + arow) * K) + aseg;
    const char* bSrcH0 = (const char*)(Wh + ((size_t)d * K + brow) * N + n0) + bseg;
    const char* bSrcL0 = (const char*)(Wl + ((size_t)d * K + brow) * N + n0) + bseg;
    const uint32_t aDstH = ubase + arow * 80 + aseg;
    const uint32_t aDstL = aDstH + 5120;
    const uint32_t bDstH0 = ubase + 10240 + brow * 272 + bseg;
    const uint32_t bDstL0 = bDstH0 + 8704;

#define COPYC(c, s)                                                           \
    {                                                                         \
        const uint32_t so = (uint32_t)((s) * STAGEB);                         \
        const size_t akb = (size_t)(c) * 64;         /* 32 k * 2B */          \
        const size_t bkb = (size_t)(c) * 32 * N * 2; /* 32 k rows */          \
        CP16(aDstH + so, aSrcH + akb);                                        \
        CP16(aDstL + so, aSrcL + akb);                                        \
        CP16(bDstH0 + so, bSrcH0 + bkb);                                      \
        CP16(bDstH0 + so + 16 * 272, bSrcH0 + bkb + (size_t)16 * N * 2);      \
        CP16(bDstL0 + so, bSrcL0 + bkb);                                      \
        CP16(bDstL0 + so + 16 * 272, bSrcL0 + bkb + (size_t)16 * N * 2);      \
    }

    // prologue: stages 0..STAGES-2
    COPYC(0, 0); CP_COMMIT();
    COPYC(1, 1); CP_COMMIT();

    float acc[MT_W][4][4];
#pragma unroll
    for (int i = 0; i < MT_W; i++)
#pragma unroll
        for (int j = 0; j < 4; j++)
#pragma unroll
            for (int q = 0; q < 4; q++) acc[i][j][q] = 0.f;

    // fragment read addresses
    const int Lrow = (lane & 7) + ((lane >> 3) & 1) * 8;
    const int Lk16 = (lane >> 4) & 1;
    const uint32_t aOff = ubase + (uint32_t)((mw * 32 + Lrow) * 80 + Lk16 * 16);
    const int bm = lane >> 3;
    const int bk = (bm & 1) * 8 + (lane & 7);
    const int bn = nw * 32 + (bm >> 1) * 8;
    const uint32_t bOff = ubase + 10240 + (uint32_t)(bk * 272 + bn * 2);

    for (int c = 0; c < NCH; c++) {
        const int s = c % STAGES;
        CP_WAIT1();
        __syncthreads();
        if (c + 2 < NCH) COPYC(c + 2, (c + 2) % STAGES);
        CP_COMMIT();

        const uint32_t aHi = aOff + (uint32_t)(s * STAGEB);
        const uint32_t aLo = aHi + 5120;
        const uint32_t bHi = bOff + (uint32_t)(s * STAGEB);
        const uint32_t bLo = bHi + 8704;
#pragma unroll
        for (int ks = 0; ks < 2; ks++) {
            uint32_t ah[MT_W][4], al[MT_W][4];
#pragma unroll
            for (int mt = 0; mt < MT_W; mt++) {
                LDSM_X4(ah[mt], aHi + mt * (16 * 80) + ks * 32);
                LDSM_X4(al[mt], aLo + mt * (16 * 80) + ks * 32);
            }
            uint32_t bh[4][2], bl[4][2];
#pragma unroll
            for (int np = 0; np < 2; np++) {
                LDSM_X4T(bh[2 * np][0], bh[2 * np][1],
                         bh[2 * np + 1][0], bh[2 * np + 1][1],
                         bHi + ks * (16 * 272) + np * 32);
                LDSM_X4T(bl[2 * np][0], bl[2 * np][1],
                         bl[2 * np + 1][0], bl[2 * np + 1][1],
                         bLo + ks * (16 * 272) + np * 32);
            }
#pragma unroll
            for (int nt = 0; nt < 4; nt++)
#pragma unroll
                for (int mt = 0; mt < MT_W; mt++)
                    MMA_BF16(acc[mt][nt], ah[mt], bh[nt][0], bh[nt][1]);
#pragma unroll
            for (int nt = 0; nt < 4; nt++)
#pragma unroll
                for (int mt = 0; mt < MT_W; mt++)
                    MMA_BF16(acc[mt][nt], ah[mt], bl[nt][0], bl[nt][1]);
#pragma unroll
            for (int nt = 0; nt < 4; nt++)
#pragma unroll
                for (int mt = 0; mt < MT_W; mt++)
                    MMA_BF16(acc[mt][nt], al[mt], bh[nt][0], bh[nt][1]);
        }
        __syncthreads();
    }

    // ---------------- epilogue: bias + relu + store ----------------
#pragma unroll
    for (int mt = 0; mt < MT_W; mt++) {
#pragma unroll
        for (int half = 0; half < 2; half++) {
            int mrow = mw * 32 + mt * 16 + grp + half * 8;
            int r = m0 + mrow;
            if (r < len) {
#pragma unroll
                for (int nt = 0; nt < 4; nt++) {
                    int col = nw * 32 + nt * 8 + 2 * tig;
                    float ox = fmaxf(acc[mt][nt][half * 2 + 0] + biasS[col], 0.f);
                    float oy = fmaxf(acc[mt][nt][half * 2 + 1] + biasS[col + 1], 0.f);
                    if (LAYER == 2) {
                        int orow = g_perm[off + r];
                        float2 o = make_float2(ox, oy);
                        *(float2*)(outp + (size_t)orow * N + n0 + col) = o;
                    } else {
                        uint32_t hv, lv;
                        split2(ox, oy, hv, lv);
                        size_t o = (size_t)(off + r) * N + n0 + col;
                        *(uint32_t*)(Ch + o) = hv;
                        *(uint32_t*)(Cl + o) = lv;
                    }
                }
            }
        }
    }
}

// ---------------- launch ----------------
extern "C" void kernel_launch(void* const* d_in, const int* in_sizes, int n_in,
                              void* d_out, int out_size) {
    const float* x   = (const float*)d_in[0];
    const int*   ind = (const int*)  d_in[1];
    const float* sk0 = (const float*)d_in[2];
    const float* sb0 = (const float*)d_in[3];
    const float* dk0 = (const float*)d_in[4];
    const float* db0 = (const float*)d_in[5];
    const float* sk1 = (const float*)d_in[6];
    const float* sb1 = (const float*)d_in[7];
    const float* dk1 = (const float*)d_in[8];
    const float* db1 = (const float*)d_in[9];
    const float* sk2 = (const float*)d_in[10];
    const float* sb2 = (const float*)d_in[11];
    const float* dk2 = (const float*)d_in[12];
    const float* db2 = (const float*)d_in[13];
    float* out = (float*)d_out;

    cudaFuncSetAttribute(gemm_mma<0>, cudaFuncAttributeMaxDynamicSharedMemorySize, GEMM_SMEM);
    cudaFuncSetAttribute(gemm_mma<1>, cudaFuncAttributeMaxDynamicSharedMemorySize, GEMM_SMEM);
    cudaFuncSetAttribute(gemm_mma<2>, cudaFuncAttributeMaxDynamicSharedMemorySize, GEMM_SMEM);

    build_perm<<<1, 256>>>(ind);
    prep_x<<<(B_ROWS * D0 / 4 + 255) / 256, 256>>>(x);
    prep_w<0><<<(NDOM * D0 * D1 / 4 + 255) / 256, 256>>>(sk0, dk0);
    prep_w<1><<<(NDOM * D1 * D2 / 4 + 255) / 256, 256>>>(sk1, dk1);
    prep_w<2><<<(NDOM * D2 * D3 / 4 + 255) / 256, 256>>>(sk2, dk2);

    gemm_mma<0><<<dim3(D1 / 128, MAXT64), 256, GEMM_SMEM>>>(sb0, db0, nullptr);
    gemm_mma<1><<<dim3(D2 / 128, MAXT64), 256, GEMM_SMEM>>>(sb1, db1, nullptr);
    gemm_mma<2><<<dim3(D3 / 128, MAXT64), 256, GEMM_SMEM>>>(sb2, db2, out);
}

// round 13
// speedup vs baseline: 1.0634x; 1.0084x over previous
#include <cuda_runtime.h>
#include <cuda_bf16.h>
#include <cstdint>

// Problem constants
#define B_ROWS 4096
#define NDOM 8
#define D0 1024
#define D1 1024
#define D2 512
#define D3 256
#define MAXT64 72
#define MTILE 64
#define STAGES 3
#define PADR 64
#define THREADS 512

// ---------------- device scratch ----------------
__device__ int   g_perm[B_ROWS];
__device__ int   g_off[NDOM + 1];
__device__ int   g_tile_d64[MAXT64];
__device__ int   g_tile_m64[MAXT64];
__device__ int   g_nt64;
// bf16 hi/lo planes: activations (sorted order) and fused weights [d][k][n]
__device__ __nv_bfloat16 g_xh[(B_ROWS + PADR) * D0];
__device__ __nv_bfloat16 g_xl[(B_ROWS + PADR) * D0];
__device__ __nv_bfloat16 g_h1h[(B_ROWS + PADR) * D1];
__device__ __nv_bfloat16 g_h1l[(B_ROWS + PADR) * D1];
__device__ __nv_bfloat16 g_h2h[(B_ROWS + PADR) * D2];
__device__ __nv_bfloat16 g_h2l[(B_ROWS + PADR) * D2];
__device__ __nv_bfloat16 g_w0h[NDOM * D0 * D1];
__device__ __nv_bfloat16 g_w0l[NDOM * D0 * D1];
__device__ __nv_bfloat16 g_w1h[NDOM * D1 * D2];
__device__ __nv_bfloat16 g_w1l[NDOM * D1 * D2];
__device__ __nv_bfloat16 g_w2h[NDOM * D2 * D3];
__device__ __nv_bfloat16 g_w2l[NDOM * D2 * D3];

#define MMA_BF16(d, a, b0, b1)                                                \
    asm volatile(                                                             \
        "mma.sync.aligned.m16n8k16.row.col.f32.bf16.bf16.f32 "                \
        "{%0,%1,%2,%3}, {%4,%5,%6,%7}, {%8,%9}, {%0,%1,%2,%3};"               \
        : "+f"((d)[0]), "+f"((d)[1]), "+f"((d)[2]), "+f"((d)[3])              \
        : "r"((a)[0]), "r"((a)[1]), "r"((a)[2]), "r"((a)[3]),                 \
          "r"(b0), "r"(b1))

#define LDSM_X4(r, addr)                                                      \
    asm volatile("ldmatrix.sync.aligned.m8n8.x4.shared.b16 "                  \
                 "{%0,%1,%2,%3}, [%4];"                                       \
                 : "=r"((r)[0]), "=r"((r)[1]), "=r"((r)[2]), "=r"((r)[3])     \
                 : "r"(addr))

#define LDSM_X4T(r0, r1, r2, r3, addr)                                        \
    asm volatile("ldmatrix.sync.aligned.m8n8.x4.trans.shared.b16 "            \
                 "{%0,%1,%2,%3}, [%4];"                                       \
                 : "=r"(r0), "=r"(r1), "=r"(r2), "=r"(r3)                     \
                 : "r"(addr))

#define CP16(dst, src)                                                        \
    asm volatile("cp.async.cg.shared.global [%0], [%1], 16;"                  \
                 :: "r"(dst), "l"(src))
#define CP_COMMIT() asm volatile("cp.async.commit_group;" ::: "memory")
#define CP_WAIT1()  asm volatile("cp.async.wait_group 1;" ::: "memory")

// split fp32 pair -> bf16 hi/lo packed words
__device__ __forceinline__ void split2(float x, float y,
                                       uint32_t& hi, uint32_t& lo) {
    __nv_bfloat162 h = __floats2bfloat162_rn(x, y);
    float2 f = __bfloat1622float2(h);
    __nv_bfloat162 l = __floats2bfloat162_rn(x - f.x, y - f.y);
    hi = *(uint32_t*)&h;
    lo = *(uint32_t*)&l;
}

// ---------------- permutation + tile list ----------------
__global__ void build_perm(const int* __restrict__ ind) {
    __shared__ int cnt[NDOM];
    __shared__ int cur[NDOM];
    int t = threadIdx.x;
    if (t < NDOM) cnt[t] = 0;
    __syncthreads();
    for (int i = t; i < B_ROWS; i += blockDim.x) atomicAdd(&cnt[ind[i]], 1);
    __syncthreads();
    if (t == 0) {
        int s = 0;
        for (int d = 0; d < NDOM; d++) { g_off[d] = s; cur[d] = s; s += cnt[d]; }
        g_off[NDOM] = s;
        int n64 = 0;
        for (int d = 0; d < NDOM; d++) {
            int len = g_off[d + 1] - g_off[d];
            for (int m0 = 0; m0 < len; m0 += MTILE) {
                g_tile_d64[n64] = d; g_tile_m64[n64] = m0; n64++;
            }
        }
        g_nt64 = n64;
    }
    __syncthreads();
    for (int i = t; i < B_ROWS; i += blockDim.x) {
        int d = ind[i];
        int p = atomicAdd(&cur[d], 1);
        g_perm[p] = i;
    }
}

// ---------------- prepass: gather + split x into sorted bf16 planes --------
__global__ void prep_x(const float* __restrict__ x) {
    int i = blockIdx.x * 256 + threadIdx.x;       // one float4
    if (i >= B_ROWS * D0 / 4) return;
    int row = i / (D0 / 4);
    int c4  = (i % (D0 / 4)) * 4;
    int prow = g_perm[row];
    float4 v = *(const float4*)(x + (size_t)prow * D0 + c4);
    uint32_t h0, l0, h1, l1;
    split2(v.x, v.y, h0, l0);
    split2(v.z, v.w, h1, l1);
    uint2 hv = make_uint2(h0, h1), lv = make_uint2(l0, l1);
    *(uint2*)(g_xh + (size_t)row * D0 + c4) = hv;
    *(uint2*)(g_xl + (size_t)row * D0 + c4) = lv;
}

// ---------------- prepass: fuse sk*dk, split to bf16 planes ----------------
template <int LAYER>
__global__ void prep_w(const float* __restrict__ sk, const float* __restrict__ dk) {
    constexpr int K = (LAYER == 0) ? D0 : (LAYER == 1) ? D1 : D2;
    constexpr int N = (LAYER == 0) ? D1 : (LAYER == 1) ? D2 : D3;
    __nv_bfloat16* wh = (LAYER == 0) ? g_w0h : (LAYER == 1) ? g_w1h : g_w2h;
    __nv_bfloat16* wl = (LAYER == 0) ? g_w0l : (LAYER == 1) ? g_w1l : g_w2l;
    int i = blockIdx.x * 256 + threadIdx.x;
    if (i >= NDOM * K * N / 4) return;
    int idx = i * 4;
    int kn  = idx % (K * N);
    float4 s = *(const float4*)(sk + kn);
    float4 t = *(const float4*)(dk + idx);
    float4 w;
    w.x = s.x * t.x; w.y = s.y * t.y; w.z = s.z * t.z; w.w = s.w * t.w;
    uint32_t h0, l0, h1, l1;
    split2(w.x, w.y, h0, l0);
    split2(w.z, w.w, h1, l1);
    *(uint2*)(wh + idx) = make_uint2(h0, h1);
    *(uint2*)(wl + idx) = make_uint2(l0, l1);
}

// ---------------- smem stage layout (bytes) ----------------
// aHi: 64 rows x 64B @80B stride (5120) | aLo +5120
// bHi: 32 rows x 256B @272B stride (8704) @10240 | bLo @18944
#define STAGEB 27648
#define GEMM_SMEM (STAGES * STAGEB + 512)   // ~83.5 KB -> 2 CTAs/SM

// ---------------- bf16 split (3-product) grouped GEMM, cp.async loader -----
// Block tile 64 x 128, K-chunk 32, 3-stage cp.async pipeline.
// 512 threads = 16 warps (4M x 4N), warp tile 16 x 32 -> 8 warps/SMSP @2 CTA.
template <int LAYER>
__global__ __launch_bounds__(THREADS, 2)
void gemm_mma(const float* __restrict__ sb, const float* __restrict__ db,
              float* __restrict__ outp) {
    constexpr int K = (LAYER == 0) ? D0 : (LAYER == 1) ? D1 : D2;
    constexpr int N = (LAYER == 0) ? D1 : (LAYER == 1) ? D2 : D3;
    constexpr int NCH = K / 32;

    const int tyb = blockIdx.y;
    if (tyb >= g_nt64) return;
    const int d   = g_tile_d64[tyb];
    const int m0  = g_tile_m64[tyb];
    const int off = g_off[d];
    const int len = g_off[d + 1] - off;
    const int n0  = blockIdx.x * 128;
    const int gmrow0 = off + m0;              // sorted-order global row base

    extern __shared__ char smc[];
    float* biasS = (float*)(smc + STAGES * STAGEB);

    const int tid  = threadIdx.x;
    const int lane = tid & 31;
    const int w    = tid >> 5;
    const int mw   = w >> 2;        // 0..3 -> M offset mw*16
    const int nw   = w & 3;         // 0..3 -> N offset nw*32
    const int grp  = lane >> 2;
    const int tig  = lane & 3;

    if (tid >= 128 && tid < 160) {
        int q = tid - 128;
        float4 a = *(const float4*)(sb + n0 + q * 4);
        float4 b = *(const float4*)(db + (size_t)d * N + n0 + q * 4);
        a.x += b.x; a.y += b.y; a.z += b.z; a.w += b.w;
        *(float4*)(biasS + q * 4) = a;
    }

    const __nv_bfloat16* Ah = (LAYER == 0) ? g_xh : (LAYER == 1) ? g_h1h : g_h2h;
    const __nv_bfloat16* Al = (LAYER == 0) ? g_xl : (LAYER == 1) ? g_h1l : g_h2l;
    const __nv_bfloat16* Wh = (LAYER == 0) ? g_w0h : (LAYER == 1) ? g_w1h : g_w2h;
    const __nv_bfloat16* Wl = (LAYER == 0) ? g_w0l : (LAYER == 1) ? g_w1l : g_w2l;
    __nv_bfloat16* Ch = (LAYER == 0) ? g_h1h : g_h2h;
    __nv_bfloat16* Cl = (LAYER == 0) ? g_h1l : g_h2l;

    const uint32_t ubase = (uint32_t)__cvta_generic_to_shared(smc);

    // copy coords: 1 A seg + 2 B segs per thread
    const int aplane = tid >> 8;               // 0 hi, 1 lo
    const int arow   = (tid & 255) >> 2;       // 0..63
    const int aseg   = (tid & 3) * 16;
    const int brow   = tid >> 4;               // 0..31
    const int bseg   = (tid & 15) * 16;

    const __nv_bfloat16* Asel = aplane ? Al : Ah;
    const char* aSrc  = (const char*)(Asel + (size_t)(gmrow0 + arow) * K) + aseg;
    const char* bSrcH = (const char*)(Wh + ((size_t)d * K + brow) * N + n0) + bseg;
    const char* bSrcL = (const char*)(Wl + ((size_t)d * K + brow) * N + n0) + bseg;
    const uint32_t aDst  = ubase + aplane * 5120 + arow * 80 + aseg;
    const uint32_t bDstH = ubase + 10240 + brow * 272 + bseg;
    const uint32_t bDstL = bDstH + 8704;

#define COPYC(c, s)                                                           \
    {                                                                         \
        const uint32_t so = (uint32_t)((s) * STAGEB);                         \
        const size_t akb = (size_t)(c) * 64;         /* 32 k * 2B */          \
        const size_t bkb = (size_t)(c) * 32 * N * 2; /* 32 k rows */          \
        CP16(aDst + so, aSrc + akb);                                          \
        CP16(bDstH + so, bSrcH + bkb);                                        \
        CP16(bDstL + so, bSrcL + bkb);                                        \
    }

    // prologue: stages 0..STAGES-2
    COPYC(0, 0); CP_COMMIT();
    COPYC(1, 1); CP_COMMIT();

    float acc[4][4];
#pragma unroll
    for (int j = 0; j < 4; j++)
#pragma unroll
        for (int q = 0; q < 4; q++) acc[j][q] = 0.f;

    // fragment read addresses
    const int Lrow = (lane & 7) + ((lane >> 3) & 1) * 8;
    const int Lk16 = (lane >> 4) & 1;
    const uint32_t aOff = ubase + (uint32_t)((mw * 16 + Lrow) * 80 + Lk16 * 16);
    const int bm = lane >> 3;
    const int bk = (bm & 1) * 8 + (lane & 7);
    const int bn = nw * 32 + (bm >> 1) * 8;
    const uint32_t bOff = ubase + 10240 + (uint32_t)(bk * 272 + bn * 2);

    for (int c = 0; c < NCH; c++) {
        const int s = c % STAGES;
        CP_WAIT1();
        __syncthreads();
        if (c + 2 < NCH) COPYC(c + 2, (c + 2) % STAGES);
        CP_COMMIT();

        const uint32_t aHi = aOff + (uint32_t)(s * STAGEB);
        const uint32_t aLo = aHi + 5120;
        const uint32_t bHi = bOff + (uint32_t)(s * STAGEB);
        const uint32_t bLo = bHi + 8704;
#pragma unroll
        for (int ks = 0; ks < 2; ks++) {
            uint32_t ah[4], al[4];
            LDSM_X4(ah, aHi + ks * 32);
            LDSM_X4(al, aLo + ks * 32);
            uint32_t bh[4][2], bl[4][2];
#pragma unroll
            for (int np = 0; np < 2; np++) {
                LDSM_X4T(bh[2 * np][0], bh[2 * np][1],
                         bh[2 * np + 1][0], bh[2 * np + 1][1],
                         bHi + ks * (16 * 272) + np * 32);
                LDSM_X4T(bl[2 * np][0], bl[2 * np][1],
                         bl[2 * np + 1][0], bl[2 * np + 1][1],
                         bLo + ks * (16 * 272) + np * 32);
            }
#pragma unroll
            for (int nt = 0; nt < 4; nt++)
                MMA_BF16(acc[nt], ah, bh[nt][0], bh[nt][1]);
#pragma unroll
            for (int nt = 0; nt < 4; nt++)
                MMA_BF16(acc[nt], ah, bl[nt][0], bl[nt][1]);
#pragma unroll
            for (int nt = 0; nt < 4; nt++)
                MMA_BF16(acc[nt], al, bh[nt][0], bh[nt][1]);
        }
        __syncthreads();
    }

    // ---------------- epilogue: bias + relu + store ----------------
#pragma unroll
    for (int half = 0; half < 2; half++) {
        int mrow = mw * 16 + grp + half * 8;
        int r = m0 + mrow;
        if (r < len) {
#pragma unroll
            for (int nt = 0; nt < 4; nt++) {
                int col = nw * 32 + nt * 8 + 2 * tig;
                float ox = fmaxf(acc[nt][half * 2 + 0] + biasS[col], 0.f);
                float oy = fmaxf(acc[nt][half * 2 + 1] + biasS[col + 1], 0.f);
                if (LAYER == 2) {
                    int orow = g_perm[off + r];
                    float2 o = make_float2(ox, oy);
                    *(float2*)(outp + (size_t)orow * N + n0 + col) = o;
                } else {
                    uint32_t hv, lv;
                    split2(ox, oy, hv, lv);
                    size_t o = (size_t)(off + r) * N + n0 + col;
                    *(uint32_t*)(Ch + o) = hv;
                    *(uint32_t*)(Cl + o) = lv;
                }
            }
        }
    }
}

// ---------------- launch ----------------
extern "C" void kernel_launch(void* const* d_in, const int* in_sizes, int n_in,
                              void* d_out, int out_size) {
    const float* x   = (const float*)d_in[0];
    const int*   ind = (const int*)  d_in[1];
    const float* sk0 = (const float*)d_in[2];
    const float* sb0 = (const float*)d_in[3];
    const float* dk0 = (const float*)d_in[4];
    const float* db0 = (const float*)d_in[5];
    const float* sk1 = (const float*)d_in[6];
    const float* sb1 = (const float*)d_in[7];
    const float* dk1 = (const float*)d_in[8];
    const float* db1 = (const float*)d_in[9];
    const float* sk2 = (const float*)d_in[10];
    const float* sb2 = (const float*)d_in[11];
    const float* dk2 = (const float*)d_in[12];
    const float* db2 = (const float*)d_in[13];
    float* out = (float*)d_out;

    cudaFuncSetAttribute(gemm_mma<0>, cudaFuncAttributeMaxDynamicSharedMemorySize, GEMM_SMEM);
    cudaFuncSetAttribute(gemm_mma<1>, cudaFuncAttributeMaxDynamicSharedMemorySize, GEMM_SMEM);
    cudaFuncSetAttribute(gemm_mma<2>, cudaFuncAttributeMaxDynamicSharedMemorySize, GEMM_SMEM);

    build_perm<<<1, 256>>>(ind);
    prep_x<<<(B_ROWS * D0 / 4 + 255) / 256, 256>>>(x);
    prep_w<0><<<(NDOM * D0 * D1 / 4 + 255) / 256, 256>>>(sk0, dk0);
    prep_w<1><<<(NDOM * D1 * D2 / 4 + 255) / 256, 256>>>(sk1, dk1);
    prep_w<2><<<(NDOM * D2 * D3 / 4 + 255) / 256, 256>>>(sk2, dk2);

    gemm_mma<0><<<dim3(D1 / 128, MAXT64), THREADS, GEMM_SMEM>>>(sb0, db0, nullptr);
    gemm_mma<1><<<dim3(D2 / 128, MAXT64), THREADS, GEMM_SMEM>>>(sb1, db1, nullptr);
    gemm_mma<2><<<dim3(D3 / 128, MAXT64), THREADS, GEMM_SMEM>>>(sb2, db2, out);
}

// round 14
// speedup vs baseline: 1.4013x; 1.3178x over previous
#include <cuda_runtime.h>
#include <cuda_fp16.h>
#include <cstdint>

// Problem constants
#define B_ROWS 4096
#define NDOM 8
#define D0 1024
#define D1 1024
#define D2 512
#define D3 256
#define MAXT64 72
#define MTILE 64
#define PADR 64
#define STAGES 3

// ---------------- device scratch ----------------
__device__ int   g_perm[B_ROWS];
__device__ int   g_off[NDOM + 1];
__device__ int   g_tile_d64[MAXT64];
__device__ int   g_tile_m64[MAXT64];
__device__ int   g_nt64;
// fp16 planes: activations hi/lo (sorted order), fused weights single plane
__device__ __half g_xh[(B_ROWS + PADR) * D0];
__device__ __half g_xl[(B_ROWS + PADR) * D0];
__device__ __half g_h1h[(B_ROWS + PADR) * D1];
__device__ __half g_h1l[(B_ROWS + PADR) * D1];
__device__ __half g_h2h[(B_ROWS + PADR) * D2];
__device__ __half g_h2l[(B_ROWS + PADR) * D2];
__device__ __half g_w0[NDOM * D0 * D1];
__device__ __half g_w1[NDOM * D1 * D2];
__device__ __half g_w2[NDOM * D2 * D3];

#define MMA_F16(d, a, b0, b1)                                                 \
    asm volatile(                                                             \
        "mma.sync.aligned.m16n8k16.row.col.f32.f16.f16.f32 "                  \
        "{%0,%1,%2,%3}, {%4,%5,%6,%7}, {%8,%9}, {%0,%1,%2,%3};"               \
        : "+f"((d)[0]), "+f"((d)[1]), "+f"((d)[2]), "+f"((d)[3])              \
        : "r"((a)[0]), "r"((a)[1]), "r"((a)[2]), "r"((a)[3]),                 \
          "r"(b0), "r"(b1))

#define LDSM_X4(r, addr)                                                      \
    asm volatile("ldmatrix.sync.aligned.m8n8.x4.shared.b16 "                  \
                 "{%0,%1,%2,%3}, [%4];"                                       \
                 : "=r"((r)[0]), "=r"((r)[1]), "=r"((r)[2]), "=r"((r)[3])     \
                 : "r"(addr))

#define LDSM_X4T(r0, r1, r2, r3, addr)                                        \
    asm volatile("ldmatrix.sync.aligned.m8n8.x4.trans.shared.b16 "            \
                 "{%0,%1,%2,%3}, [%4];"                                       \
                 : "=r"(r0), "=r"(r1), "=r"(r2), "=r"(r3)                     \
                 : "r"(addr))

#define CP16(dst, src)                                                        \
    asm volatile("cp.async.cg.shared.global [%0], [%1], 16;"                  \
                 :: "r"(dst), "l"(src))
#define CP_COMMIT() asm volatile("cp.async.commit_group;" ::: "memory")
#define CP_WAIT1()  asm volatile("cp.async.wait_group 1;" ::: "memory")

// split fp32 pair -> fp16 hi/lo packed words
__device__ __forceinline__ void split2h(float x, float y,
                                        uint32_t& hi, uint32_t& lo) {
    __half2 h = __floats2half2_rn(x, y);
    float2 f = __half22float2(h);
    __half2 l = __floats2half2_rn(x - f.x, y - f.y);
    hi = *(uint32_t*)&h;
    lo = *(uint32_t*)&l;
}

// ---------------- permutation + tile list ----------------
__global__ void build_perm(const int* __restrict__ ind) {
    __shared__ int cnt[NDOM];
    __shared__ int cur[NDOM];
    int t = threadIdx.x;
    if (t < NDOM) cnt[t] = 0;
    __syncthreads();
    for (int i = t; i < B_ROWS; i += blockDim.x) atomicAdd(&cnt[ind[i]], 1);
    __syncthreads();
    if (t == 0) {
        int s = 0;
        for (int d = 0; d < NDOM; d++) { g_off[d] = s; cur[d] = s; s += cnt[d]; }
        g_off[NDOM] = s;
        int n64 = 0;
        for (int d = 0; d < NDOM; d++) {
            int len = g_off[d + 1] - g_off[d];
            for (int m0 = 0; m0 < len; m0 += MTILE) {
                g_tile_d64[n64] = d; g_tile_m64[n64] = m0; n64++;
            }
        }
        g_nt64 = n64;
    }
    __syncthreads();
    for (int i = t; i < B_ROWS; i += blockDim.x) {
        int d = ind[i];
        int p = atomicAdd(&cur[d], 1);
        g_perm[p] = i;
    }
}

// ---------------- prepass: gather + split x into sorted fp16 planes --------
__global__ void prep_x(const float* __restrict__ x) {
    int i = blockIdx.x * 256 + threadIdx.x;       // one float4
    if (i >= B_ROWS * D0 / 4) return;
    int row = i / (D0 / 4);
    int c4  = (i % (D0 / 4)) * 4;
    int prow = g_perm[row];
    float4 v = *(const float4*)(x + (size_t)prow * D0 + c4);
    uint32_t h0, l0, h1, l1;
    split2h(v.x, v.y, h0, l0);
    split2h(v.z, v.w, h1, l1);
    *(uint2*)(g_xh + (size_t)row * D0 + c4) = make_uint2(h0, h1);
    *(uint2*)(g_xl + (size_t)row * D0 + c4) = make_uint2(l0, l1);
}

// ---------------- prepass: fuse sk*dk -> single fp16 plane ----------------
template <int LAYER>
__global__ void prep_w(const float* __restrict__ sk, const float* __restrict__ dk) {
    constexpr int K = (LAYER == 0) ? D0 : (LAYER == 1) ? D1 : D2;
    constexpr int N = (LAYER == 0) ? D1 : (LAYER == 1) ? D2 : D3;
    __half* wq = (LAYER == 0) ? g_w0 : (LAYER == 1) ? g_w1 : g_w2;
    int i = blockIdx.x * 256 + threadIdx.x;
    if (i >= NDOM * K * N / 4) return;
    int idx = i * 4;
    int kn  = idx % (K * N);
    float4 s = *(const float4*)(sk + kn);
    float4 t = *(const float4*)(dk + idx);
    __half2 a = __floats2half2_rn(s.x * t.x, s.y * t.y);
    __half2 b = __floats2half2_rn(s.z * t.z, s.w * t.w);
    *(uint2*)(wq + idx) = make_uint2(*(uint32_t*)&a, *(uint32_t*)&b);
}

// ---------------- smem stage layout (bytes) ----------------
// A: 2 planes x 64 rows x 128B (K-chunk 64), row stride 144B -> 9216/plane
// B: 64 k-rows x 256B, row stride 272B -> 17408
#define APL    9216
#define ABYT   18432
#define STAGEB 35840
#define GEMM_SMEM (STAGES * STAGEB + 512)   // ~105.5 KB -> 2 CTAs/SM

// ---------------- fp16 2-product grouped GEMM, cp.async loader -------------
// Block tile 64 x 128, K-chunk 64, 3-stage cp.async pipeline, 256 threads /
// 8 warps (2M x 4N), warp tile 32 x 32. D = Ah*W + Al*W, W single fp16.
template <int LAYER>
__global__ __launch_bounds__(256, 2)
void gemm_mma(const float* __restrict__ sb, const float* __restrict__ db,
              float* __restrict__ outp) {
    constexpr int K = (LAYER == 0) ? D0 : (LAYER == 1) ? D1 : D2;
    constexpr int N = (LAYER == 0) ? D1 : (LAYER == 1) ? D2 : D3;
    constexpr int NCH = K / 64;

    const int tyb = blockIdx.y;
    if (tyb >= g_nt64) return;
    const int d   = g_tile_d64[tyb];
    const int m0  = g_tile_m64[tyb];
    const int off = g_off[d];
    const int len = g_off[d + 1] - off;
    const int n0  = blockIdx.x * 128;
    const int gmrow0 = off + m0;

    extern __shared__ char smc[];
    float* biasS = (float*)(smc + STAGES * STAGEB);

    const int tid  = threadIdx.x;
    const int lane = tid & 31;
    const int w    = tid >> 5;
    const int mw   = w >> 2;        // 0..1 -> M offset mw*32
    const int nw   = w & 3;         // 0..3 -> N offset nw*32
    const int grp  = lane >> 2;
    const int tig  = lane & 3;

    if (tid >= 128 && tid < 160) {
        int q = tid - 128;
        float4 a = *(const float4*)(sb + n0 + q * 4);
        float4 b = *(const float4*)(db + (size_t)d * N + n0 + q * 4);
        a.x += b.x; a.y += b.y; a.z += b.z; a.w += b.w;
        *(float4*)(biasS + q * 4) = a;
    }

    const __half* Ah = (LAYER == 0) ? g_xh : (LAYER == 1) ? g_h1h : g_h2h;
    const __half* Al = (LAYER == 0) ? g_xl : (LAYER == 1) ? g_h1l : g_h2l;
    const __half* Wq = (LAYER == 0) ? g_w0 : (LAYER == 1) ? g_w1 : g_w2;
    __half* Ch = (LAYER == 0) ? g_h1h : g_h2h;
    __half* Cl = (LAYER == 0) ? g_h1l : g_h2l;

    const uint32_t ubase = (uint32_t)__cvta_generic_to_shared(smc);

    // copy coords: per i in 0..3 -> one A seg; per i in 0..3 -> one B seg
    const char* aSrc[4];
    uint32_t    aDst[4];
    const char* bSrc[4];
    uint32_t    bDst[4];
#pragma unroll
    for (int i = 0; i < 4; i++) {
        int idx  = tid + i * 256;             // 0..1023
        int apl  = idx >> 9;                  // plane
        int arow = (idx >> 3) & 63;
        int aseg = (idx & 7) * 16;
        const __half* Asel = apl ? Al : Ah;
        aSrc[i] = (const char*)(Asel + (size_t)(gmrow0 + arow) * K) + aseg;
        aDst[i] = ubase + apl * APL + arow * 144 + aseg;
        int brow = idx >> 4;                  // 0..63
        int bseg = (idx & 15) * 16;
        bSrc[i] = (const char*)(Wq + ((size_t)d * K + brow) * N + n0) + bseg;
        bDst[i] = ubase + ABYT + brow * 272 + bseg;
    }

#define COPYC(c, s)                                                           \
    {                                                                         \
        const uint32_t so  = (uint32_t)((s) * STAGEB);                        \
        const size_t   akb = (size_t)(c) * 128;          /* 64 k * 2B */      \
        const size_t   bkb = (size_t)(c) * 64 * N * 2;   /* 64 k rows */      \
        _Pragma("unroll")                                                     \
        for (int i = 0; i < 4; i++) CP16(aDst[i] + so, aSrc[i] + akb);        \
        _Pragma("unroll")                                                     \
        for (int i = 0; i < 4; i++) CP16(bDst[i] + so, bSrc[i] + bkb);        \
    }

    // prologue
    COPYC(0, 0); CP_COMMIT();
    COPYC(1, 1); CP_COMMIT();

    float acc[2][4][4];
#pragma unroll
    for (int i = 0; i < 2; i++)
#pragma unroll
        for (int j = 0; j < 4; j++)
#pragma unroll
            for (int q = 0; q < 4; q++) acc[i][j][q] = 0.f;

    // fragment read addresses
    const int Lrow = (lane & 7) + ((lane >> 3) & 1) * 8;
    const int Lk16 = (lane >> 4) & 1;
    const uint32_t aOff = ubase + (uint32_t)((mw * 32 + Lrow) * 144 + Lk16 * 16);
    const int bm = lane >> 3;
    const int bk = (bm & 1) * 8 + (lane & 7);
    const int bn = nw * 32 + (bm >> 1) * 8;
    const uint32_t bOff = ubase + ABYT + (uint32_t)(bk * 272 + bn * 2);

    for (int c = 0; c < NCH; c++) {
        const int s = c % STAGES;
        CP_WAIT1();
        __syncthreads();
        if (c + 2 < NCH) COPYC(c + 2, (c + 2) % STAGES);
        CP_COMMIT();

        const uint32_t aHi = aOff + (uint32_t)(s * STAGEB);
        const uint32_t aLo = aHi + APL;
        const uint32_t bBs = bOff + (uint32_t)(s * STAGEB);
#pragma unroll
        for (int ks = 0; ks < 4; ks++) {
            uint32_t ah[2][4], al[2][4];
#pragma unroll
            for (int mt = 0; mt < 2; mt++) {
                LDSM_X4(ah[mt], aHi + mt * (16 * 144) + ks * 32);
                LDSM_X4(al[mt], aLo + mt * (16 * 144) + ks * 32);
            }
            uint32_t bq[4][2];
#pragma unroll
            for (int np = 0; np < 2; np++) {
                LDSM_X4T(bq[2 * np][0], bq[2 * np][1],
                         bq[2 * np + 1][0], bq[2 * np + 1][1],
                         bBs + ks * (16 * 272) + np * 32);
            }
#pragma unroll
            for (int nt = 0; nt < 4; nt++)
#pragma unroll
                for (int mt = 0; mt < 2; mt++)
                    MMA_F16(acc[mt][nt], ah[mt], bq[nt][0], bq[nt][1]);
#pragma unroll
            for (int nt = 0; nt < 4; nt++)
#pragma unroll
                for (int mt = 0; mt < 2; mt++)
                    MMA_F16(acc[mt][nt], al[mt], bq[nt][0], bq[nt][1]);
        }
        __syncthreads();
    }

    // ---------------- epilogue: bias + relu + store ----------------
#pragma unroll
    for (int mt = 0; mt < 2; mt++) {
#pragma unroll
        for (int half = 0; half < 2; half++) {
            int mrow = mw * 32 + mt * 16 + grp + half * 8;
            int r = m0 + mrow;
            if (r < len) {
#pragma unroll
                for (int nt = 0; nt < 4; nt++) {
                    int col = nw * 32 + nt * 8 + 2 * tig;
                    float ox = fmaxf(acc[mt][nt][half * 2 + 0] + biasS[col], 0.f);
                    float oy = fmaxf(acc[mt][nt][half * 2 + 1] + biasS[col + 1], 0.f);
                    if (LAYER == 2) {
                        int orow = g_perm[off + r];
                        *(float2*)(outp + (size_t)orow * N + n0 + col) =
                            make_float2(ox, oy);
                    } else {
                        uint32_t hv, lv;
                        split2h(ox, oy, hv, lv);
                        size_t o = (size_t)(off + r) * N + n0 + col;
                        *(uint32_t*)(Ch + o) = hv;
                        *(uint32_t*)(Cl + o) = lv;
                    }
                }
            }
        }
    }
}

// ---------------- launch ----------------
extern "C" void kernel_launch(void* const* d_in, const int* in_sizes, int n_in,
                              void* d_out, int out_size) {
    const float* x   = (const float*)d_in[0];
    const int*   ind = (const int*)  d_in[1];
    const float* sk0 = (const float*)d_in[2];
    const float* sb0 = (const float*)d_in[3];
    const float* dk0 = (const float*)d_in[4];
    const float* db0 = (const float*)d_in[5];
    const float* sk1 = (const float*)d_in[6];
    const float* sb1 = (const float*)d_in[7];
    const float* dk1 = (const float*)d_in[8];
    const float* db1 = (const float*)d_in[9];
    const float* sk2 = (const float*)d_in[10];
    const float* sb2 = (const float*)d_in[11];
    const float* dk2 = (const float*)d_in[12];
    const float* db2 = (const float*)d_in[13];
    float* out = (float*)d_out;

    cudaFuncSetAttribute(gemm_mma<0>, cudaFuncAttributeMaxDynamicSharedMemorySize, GEMM_SMEM);
    cudaFuncSetAttribute(gemm_mma<1>, cudaFuncAttributeMaxDynamicSharedMemorySize, GEMM_SMEM);
    cudaFuncSetAttribute(gemm_mma<2>, cudaFuncAttributeMaxDynamicSharedMemorySize, GEMM_SMEM);

    build_perm<<<1, 256>>>(ind);
    prep_x<<<(B_ROWS * D0 / 4 + 255) / 256, 256>>>(x);
    prep_w<0><<<(NDOM * D0 * D1 / 4 + 255) / 256, 256>>>(sk0, dk0);
    prep_w<1><<<(NDOM * D1 * D2 / 4 + 255) / 256, 256>>>(sk1, dk1);
    prep_w<2><<<(NDOM * D2 * D3 / 4 + 255) / 256, 256>>>(sk2, dk2);

    gemm_mma<0><<<dim3(D1 / 128, MAXT64), 256, GEMM_SMEM>>>(sb0, db0, nullptr);
    gemm_mma<1><<<dim3(D2 / 128, MAXT64), 256, GEMM_SMEM>>>(sb1, db1, nullptr);
    gemm_mma<2><<<dim3(D3 / 128, MAXT64), 256, GEMM_SMEM>>>(sb2, db2, out);
}

// round 15
// speedup vs baseline: 2.0532x; 1.4653x over previous
#include <cuda_runtime.h>
#include <cuda_fp16.h>
#include <cstdint>

// Problem constants
#define B_ROWS 4096
#define NDOM 8
#define D0 1024
#define D1 1024
#define D2 512
#define D3 256
#define MAXT64 72
#define MTILE 64
#define PADR 64
#define STAGES 3

// ---------------- device scratch ----------------
__device__ int   g_perm[B_ROWS];
__device__ int   g_off[NDOM + 1];
__device__ int   g_tile_d64[MAXT64];
__device__ int   g_tile_m64[MAXT64];
__device__ int   g_nt64;
// fp16 planes: activations (sorted order) and fused weights [d][k][n]
__device__ __half g_x [(B_ROWS + PADR) * D0];
__device__ __half g_h1[(B_ROWS + PADR) * D1];
__device__ __half g_h2[(B_ROWS + PADR) * D2];
__device__ __half g_w0[NDOM * D0 * D1];
__device__ __half g_w1[NDOM * D1 * D2];
__device__ __half g_w2[NDOM * D2 * D3];

#define MMA_F16(d, a, b0, b1)                                                 \
    asm volatile(                                                             \
        "mma.sync.aligned.m16n8k16.row.col.f32.f16.f16.f32 "                  \
        "{%0,%1,%2,%3}, {%4,%5,%6,%7}, {%8,%9}, {%0,%1,%2,%3};"               \
        : "+f"((d)[0]), "+f"((d)[1]), "+f"((d)[2]), "+f"((d)[3])              \
        : "r"((a)[0]), "r"((a)[1]), "r"((a)[2]), "r"((a)[3]),                 \
          "r"(b0), "r"(b1))

#define LDSM_X4(r, addr)                                                      \
    asm volatile("ldmatrix.sync.aligned.m8n8.x4.shared.b16 "                  \
                 "{%0,%1,%2,%3}, [%4];"                                       \
                 : "=r"((r)[0]), "=r"((r)[1]), "=r"((r)[2]), "=r"((r)[3])     \
                 : "r"(addr))

#define LDSM_X4T(r0, r1, r2, r3, addr)                                        \
    asm volatile("ldmatrix.sync.aligned.m8n8.x4.trans.shared.b16 "            \
                 "{%0,%1,%2,%3}, [%4];"                                       \
                 : "=r"(r0), "=r"(r1), "=r"(r2), "=r"(r3)                     \
                 : "r"(addr))

#define CP16(dst, src)                                                        \
    asm volatile("cp.async.cg.shared.global [%0], [%1], 16;"                  \
                 :: "r"(dst), "l"(src))
#define CP_COMMIT() asm volatile("cp.async.commit_group;" ::: "memory")
#define CP_WAIT1()  asm volatile("cp.async.wait_group 1;" ::: "memory")

// ---------------- permutation + tile list ----------------
__global__ void build_perm(const int* __restrict__ ind) {
    __shared__ int cnt[NDOM];
    __shared__ int cur[NDOM];
    int t = threadIdx.x;
    if (t < NDOM) cnt[t] = 0;
    __syncthreads();
    for (int i = t; i < B_ROWS; i += blockDim.x) atomicAdd(&cnt[ind[i]], 1);
    __syncthreads();
    if (t == 0) {
        int s = 0;
        for (int d = 0; d < NDOM; d++) { g_off[d] = s; cur[d] = s; s += cnt[d]; }
        g_off[NDOM] = s;
        int n64 = 0;
        for (int d = 0; d < NDOM; d++) {
            int len = g_off[d + 1] - g_off[d];
            for (int m0 = 0; m0 < len; m0 += MTILE) {
                g_tile_d64[n64] = d; g_tile_m64[n64] = m0; n64++;
            }
        }
        g_nt64 = n64;
    }
    __syncthreads();
    for (int i = t; i < B_ROWS; i += blockDim.x) {
        int d = ind[i];
        int p = atomicAdd(&cur[d], 1);
        g_perm[p] = i;
    }
}

// ---------------- prepass: gather + convert x into sorted fp16 plane -------
__global__ void prep_x(const float* __restrict__ x) {
    int i = blockIdx.x * 256 + threadIdx.x;       // one float4
    if (i >= B_ROWS * D0 / 4) return;
    int row = i / (D0 / 4);
    int c4  = (i % (D0 / 4)) * 4;
    int prow = g_perm[row];
    float4 v = *(const float4*)(x + (size_t)prow * D0 + c4);
    __half2 a = __floats2half2_rn(v.x, v.y);
    __half2 b = __floats2half2_rn(v.z, v.w);
    *(uint2*)(g_x + (size_t)row * D0 + c4) =
        make_uint2(*(uint32_t*)&a, *(uint32_t*)&b);
}

// ---------------- prepass: fuse sk*dk -> single fp16 plane ----------------
template <int LAYER>
__global__ void prep_w(const float* __restrict__ sk, const float* __restrict__ dk) {
    constexpr int K = (LAYER == 0) ? D0 : (LAYER == 1) ? D1 : D2;
    constexpr int N = (LAYER == 0) ? D1 : (LAYER == 1) ? D2 : D3;
    __half* wq = (LAYER == 0) ? g_w0 : (LAYER == 1) ? g_w1 : g_w2;
    int i = blockIdx.x * 256 + threadIdx.x;
    if (i >= NDOM * K * N / 8) return;
    int idx = i * 8;                              // 8 elements per thread
    int kn  = idx % (K * N);
    float4 s0 = *(const float4*)(sk + kn);
    float4 s1 = *(const float4*)(sk + kn + 4);
    float4 t0 = *(const float4*)(dk + idx);
    float4 t1 = *(const float4*)(dk + idx + 4);
    __half2 a = __floats2half2_rn(s0.x * t0.x, s0.y * t0.y);
    __half2 b = __floats2half2_rn(s0.z * t0.z, s0.w * t0.w);
    __half2 c = __floats2half2_rn(s1.x * t1.x, s1.y * t1.y);
    __half2 e = __floats2half2_rn(s1.z * t1.z, s1.w * t1.w);
    uint4 o;
    o.x = *(uint32_t*)&a; o.y = *(uint32_t*)&b;
    o.z = *(uint32_t*)&c; o.w = *(uint32_t*)&e;
    *(uint4*)(wq + idx) = o;
}

// ---------------- smem stage layout (bytes) ----------------
// A: 64 rows x 128B (K-chunk 64), row stride 144B -> 9216
// B: 64 k-rows x 256B, row stride 272B -> 17408 @9216
#define ABYT   9216
#define STAGEB 26624
#define GEMM_SMEM (STAGES * STAGEB + 512)   // ~78.5 KB -> 2 CTAs/SM

// ---------------- fp16 grouped GEMM, cp.async loader -----------------------
// Block tile 64 x 128, K-chunk 64, 3-stage cp.async pipeline, 256 threads /
// 8 warps (2M x 4N), warp tile 32 x 32. Single product D = A*W (fp32 accum).
template <int LAYER>
__global__ __launch_bounds__(256, 2)
void gemm_mma(const float* __restrict__ sb, const float* __restrict__ db,
              float* __restrict__ outp) {
    constexpr int K = (LAYER == 0) ? D0 : (LAYER == 1) ? D1 : D2;
    constexpr int N = (LAYER == 0) ? D1 : (LAYER == 1) ? D2 : D3;
    constexpr int NCH = K / 64;

    const int tyb = blockIdx.y;
    if (tyb >= g_nt64) return;
    const int d   = g_tile_d64[tyb];
    const int m0  = g_tile_m64[tyb];
    const int off = g_off[d];
    const int len = g_off[d + 1] - off;
    const int n0  = blockIdx.x * 128;
    const int gmrow0 = off + m0;

    extern __shared__ char smc[];
    float* biasS = (float*)(smc + STAGES * STAGEB);

    const int tid  = threadIdx.x;
    const int lane = tid & 31;
    const int w    = tid >> 5;
    const int mw   = w >> 2;        // 0..1 -> M offset mw*32
    const int nw   = w & 3;         // 0..3 -> N offset nw*32
    const int grp  = lane >> 2;
    const int tig  = lane & 3;

    if (tid >= 128 && tid < 160) {
        int q = tid - 128;
        float4 a = *(const float4*)(sb + n0 + q * 4);
        float4 b = *(const float4*)(db + (size_t)d * N + n0 + q * 4);
        a.x += b.x; a.y += b.y; a.z += b.z; a.w += b.w;
        *(float4*)(biasS + q * 4) = a;
    }

    const __half* Ap = (LAYER == 0) ? g_x : (LAYER == 1) ? g_h1 : g_h2;
    const __half* Wq = (LAYER == 0) ? g_w0 : (LAYER == 1) ? g_w1 : g_w2;
    __half* Cp = (LAYER == 0) ? g_h1 : g_h2;

    const uint32_t ubase = (uint32_t)__cvta_generic_to_shared(smc);

    // copy coords: 2 A segs + 4 B segs per thread
    const char* aSrc[2];
    uint32_t    aDst[2];
    const char* bSrc[4];
    uint32_t    bDst[4];
#pragma unroll
    for (int i = 0; i < 2; i++) {
        int idx  = tid + i * 256;             // 0..511
        int arow = idx >> 3;                  // 0..63
        int aseg = (idx & 7) * 16;
        aSrc[i] = (const char*)(Ap + (size_t)(gmrow0 + arow) * K) + aseg;
        aDst[i] = ubase + arow * 144 + aseg;
    }
#pragma unroll
    for (int i = 0; i < 4; i++) {
        int idx  = tid + i * 256;             // 0..1023
        int brow = idx >> 4;                  // 0..63
        int bseg = (idx & 15) * 16;
        bSrc[i] = (const char*)(Wq + ((size_t)d * K + brow) * N + n0) + bseg;
        bDst[i] = ubase + ABYT + brow * 272 + bseg;
    }

#define COPYC(c, s)                                                           \
    {                                                                         \
        const uint32_t so  = (uint32_t)((s) * STAGEB);                        \
        const size_t   akb = (size_t)(c) * 128;          /* 64 k * 2B */      \
        const size_t   bkb = (size_t)(c) * 64 * N * 2;   /* 64 k rows */      \
        _Pragma("unroll")                                                     \
        for (int i = 0; i < 2; i++) CP16(aDst[i] + so, aSrc[i] + akb);        \
        _Pragma("unroll")                                                     \
        for (int i = 0; i < 4; i++) CP16(bDst[i] + so, bSrc[i] + bkb);        \
    }

    // prologue
    COPYC(0, 0); CP_COMMIT();
    COPYC(1, 1); CP_COMMIT();

    float acc[2][4][4];
#pragma unroll
    for (int i = 0; i < 2; i++)
#pragma unroll
        for (int j = 0; j < 4; j++)
#pragma unroll
            for (int q = 0; q < 4; q++) acc[i][j][q] = 0.f;

    // fragment read addresses
    const int Lrow = (lane & 7) + ((lane >> 3) & 1) * 8;
    const int Lk16 = (lane >> 4) & 1;
    const uint32_t aOff = ubase + (uint32_t)((mw * 32 + Lrow) * 144 + Lk16 * 16);
    const int bm = lane >> 3;
    const int bk = (bm & 1) * 8 + (lane & 7);
    const int bn = nw * 32 + (bm >> 1) * 8;
    const uint32_t bOff = ubase + ABYT + (uint32_t)(bk * 272 + bn * 2);

    for (int c = 0; c < NCH; c++) {
        const int s = c % STAGES;
        CP_WAIT1();
        __syncthreads();
        if (c + 2 < NCH) COPYC(c + 2, (c + 2) % STAGES);
        CP_COMMIT();

        const uint32_t aBs = aOff + (uint32_t)(s * STAGEB);
        const uint32_t bBs = bOff + (uint32_t)(s * STAGEB);
#pragma unroll
        for (int ks = 0; ks < 4; ks++) {
            uint32_t ah[2][4];
#pragma unroll
            for (int mt = 0; mt < 2; mt++)
                LDSM_X4(ah[mt], aBs + mt * (16 * 144) + ks * 32);
            uint32_t bq[4][2];
#pragma unroll
            for (int np = 0; np < 2; np++) {
                LDSM_X4T(bq[2 * np][0], bq[2 * np][1],
                         bq[2 * np + 1][0], bq[2 * np + 1][1],
                         bBs + ks * (16 * 272) + np * 32);
            }
#pragma unroll
            for (int nt = 0; nt < 4; nt++)
#pragma unroll
                for (int mt = 0; mt < 2; mt++)
                    MMA_F16(acc[mt][nt], ah[mt], bq[nt][0], bq[nt][1]);
        }
        __syncthreads();
    }

    // ---------------- epilogue: bias + relu + store ----------------
#pragma unroll
    for (int mt = 0; mt < 2; mt++) {
#pragma unroll
        for (int half = 0; half < 2; half++) {
            int mrow = mw * 32 + mt * 16 + grp + half * 8;
            int r = m0 + mrow;
            if (r < len) {
#pragma unroll
                for (int nt = 0; nt < 4; nt++) {
                    int col = nw * 32 + nt * 8 + 2 * tig;
                    float ox = fmaxf(acc[mt][nt][half * 2 + 0] + biasS[col], 0.f);
                    float oy = fmaxf(acc[mt][nt][half * 2 + 1] + biasS[col + 1], 0.f);
                    if (LAYER == 2) {
                        int orow = g_perm[off + r];
                        *(float2*)(outp + (size_t)orow * N + n0 + col) =
                            make_float2(ox, oy);
                    } else {
                        __half2 hv = __floats2half2_rn(ox, oy);
                        *(uint32_t*)(Cp + (size_t)(off + r) * N + n0 + col) =
                            *(uint32_t*)&hv;
                    }
                }
            }
        }
    }
}

// ---------------- launch ----------------
extern "C" void kernel_launch(void* const* d_in, const int* in_sizes, int n_in,
                              void* d_out, int out_size) {
    const float* x   = (const float*)d_in[0];
    const int*   ind = (const int*)  d_in[1];
    const float* sk0 = (const float*)d_in[2];
    const float* sb0 = (const float*)d_in[3];
    const float* dk0 = (const float*)d_in[4];
    const float* db0 = (const float*)d_in[5];
    const float* sk1 = (const float*)d_in[6];
    const float* sb1 = (const float*)d_in[7];
    const float* dk1 = (const float*)d_in[8];
    const float* db1 = (const float*)d_in[9];
    const float* sk2 = (const float*)d_in[10];
    const float* sb2 = (const float*)d_in[11];
    const float* dk2 = (const float*)d_in[12];
    const float* db2 = (const float*)d_in[13];
    float* out = (float*)d_out;

    cudaFuncSetAttribute(gemm_mma<0>, cudaFuncAttributeMaxDynamicSharedMemorySize, GEMM_SMEM);
    cudaFuncSetAttribute(gemm_mma<1>, cudaFuncAttributeMaxDynamicSharedMemorySize, GEMM_SMEM);
    cudaFuncSetAttribute(gemm_mma<2>, cudaFuncAttributeMaxDynamicSharedMemorySize, GEMM_SMEM);

    build_perm<<<1, 256>>>(ind);
    prep_x<<<(B_ROWS * D0 / 4 + 255) / 256, 256>>>(x);
    prep_w<0><<<(NDOM * D0 * D1 / 8 + 255) / 256, 256>>>(sk0, dk0);
    prep_w<1><<<(NDOM * D1 * D2 / 8 + 255) / 256, 256>>>(sk1, dk1);
    prep_w<2><<<(NDOM * D2 * D3 / 8 + 255) / 256, 256>>>(sk2, dk2);

    gemm_mma<0><<<dim3(D1 / 128, MAXT64), 256, GEMM_SMEM>>>(sb0, db0, nullptr);
    gemm_mma<1><<<dim3(D2 / 128, MAXT64), 256, GEMM_SMEM>>>(sb1, db1, nullptr);
    gemm_mma<2><<<dim3(D3 / 128, MAXT64), 256, GEMM_SMEM>>>(sb2, db2, out);
}

// round 16
// speedup vs baseline: 2.1894x; 1.0663x over previous
#include <cuda_runtime.h>
#include <cuda_fp16.h>
#include <cstdint>

// Problem constants
#define B_ROWS 4096
#define NDOM 8
#define D0 1024
#define D1 1024
#define D2 512
#define D3 256
#define MAXT64 72
#define MTILE 64
#define PADR 64
#define STAGES 3

// ---------------- device scratch ----------------
__device__ int   g_perm[B_ROWS];
__device__ int   g_off[NDOM + 1];
__device__ int   g_tile_d64[MAXT64];
__device__ int   g_tile_m64[MAXT64];
__device__ int   g_nt64;
// fp16 planes: activations (sorted order) and fused weights [d][k][n]
__device__ __half g_x [(B_ROWS + PADR) * D0];
__device__ __half g_h1[(B_ROWS + PADR) * D1];
__device__ __half g_h2[(B_ROWS + PADR) * D2];
__device__ __half g_w0[NDOM * D0 * D1];
__device__ __half g_w1[NDOM * D1 * D2];
__device__ __half g_w2[NDOM * D2 * D3];

#define MMA_F16(d, a, b0, b1)                                                 \
    asm volatile(                                                             \
        "mma.sync.aligned.m16n8k16.row.col.f32.f16.f16.f32 "                  \
        "{%0,%1,%2,%3}, {%4,%5,%6,%7}, {%8,%9}, {%0,%1,%2,%3};"               \
        : "+f"((d)[0]), "+f"((d)[1]), "+f"((d)[2]), "+f"((d)[3])              \
        : "r"((a)[0]), "r"((a)[1]), "r"((a)[2]), "r"((a)[3]),                 \
          "r"(b0), "r"(b1))

#define LDSM_X4(r, addr)                                                      \
    asm volatile("ldmatrix.sync.aligned.m8n8.x4.shared.b16 "                  \
                 "{%0,%1,%2,%3}, [%4];"                                       \
                 : "=r"((r)[0]), "=r"((r)[1]), "=r"((r)[2]), "=r"((r)[3])     \
                 : "r"(addr))

#define LDSM_X4T(r0, r1, r2, r3, addr)                                        \
    asm volatile("ldmatrix.sync.aligned.m8n8.x4.trans.shared.b16 "            \
                 "{%0,%1,%2,%3}, [%4];"                                       \
                 : "=r"(r0), "=r"(r1), "=r"(r2), "=r"(r3)                     \
                 : "r"(addr))

#define CP16(dst, src)                                                        \
    asm volatile("cp.async.cg.shared.global [%0], [%1], 16;"                  \
                 :: "r"(dst), "l"(src))
#define CP_COMMIT() asm volatile("cp.async.commit_group;" ::: "memory")
#define CP_WAIT1()  asm volatile("cp.async.wait_group 1;" ::: "memory")

// ---------------- permutation + tile list ----------------
__global__ void build_perm(const int* __restrict__ ind) {
    __shared__ int cnt[NDOM];
    __shared__ int cur[NDOM];
    int t = threadIdx.x;
    if (t < NDOM) cnt[t] = 0;
    __syncthreads();
    for (int i = t; i < B_ROWS; i += blockDim.x) atomicAdd(&cnt[ind[i]], 1);
    __syncthreads();
    if (t == 0) {
        int s = 0;
        for (int d = 0; d < NDOM; d++) { g_off[d] = s; cur[d] = s; s += cnt[d]; }
        g_off[NDOM] = s;
        int n64 = 0;
        for (int d = 0; d < NDOM; d++) {
            int len = g_off[d + 1] - g_off[d];
            for (int m0 = 0; m0 < len; m0 += MTILE) {
                g_tile_d64[n64] = d; g_tile_m64[n64] = m0; n64++;
            }
        }
        g_nt64 = n64;
    }
    __syncthreads();
    for (int i = t; i < B_ROWS; i += blockDim.x) {
        int d = ind[i];
        int p = atomicAdd(&cur[d], 1);
        g_perm[p] = i;
    }
}

// ---------------- prepass: gather + convert x into sorted fp16 plane -------
// 8 elements per thread
__global__ void prep_x(const float* __restrict__ x) {
    int i = blockIdx.x * 256 + threadIdx.x;
    if (i >= B_ROWS * D0 / 8) return;
    int row = i / (D0 / 8);
    int c8  = (i % (D0 / 8)) * 8;
    int prow = g_perm[row];
    const float4* src = (const float4*)(x + (size_t)prow * D0 + c8);
    float4 v0 = __ldcs(src);
    float4 v1 = __ldcs(src + 1);
    __half2 a = __floats2half2_rn(v0.x, v0.y);
    __half2 b = __floats2half2_rn(v0.z, v0.w);
    __half2 c = __floats2half2_rn(v1.x, v1.y);
    __half2 e = __floats2half2_rn(v1.z, v1.w);
    uint4 o;
    o.x = *(uint32_t*)&a; o.y = *(uint32_t*)&b;
    o.z = *(uint32_t*)&c; o.w = *(uint32_t*)&e;
    __stcg((uint4*)(g_x + (size_t)row * D0 + c8), o);
}

// ---------------- prepass: fuse sk*dk -> single fp16 plane ----------------
// 16 elements per thread
template <int LAYER>
__global__ void prep_w(const float* __restrict__ sk, const float* __restrict__ dk) {
    constexpr int K = (LAYER == 0) ? D0 : (LAYER == 1) ? D1 : D2;
    constexpr int N = (LAYER == 0) ? D1 : (LAYER == 1) ? D2 : D3;
    __half* wq = (LAYER == 0) ? g_w0 : (LAYER == 1) ? g_w1 : g_w2;
    int i = blockIdx.x * 256 + threadIdx.x;
    if (i >= NDOM * K * N / 16) return;
    size_t idx = (size_t)i * 16;
    size_t kn  = idx % (K * N);
#pragma unroll
    for (int h = 0; h < 2; h++) {
        float4 s0 = *(const float4*)(sk + kn + h * 8);
        float4 s1 = *(const float4*)(sk + kn + h * 8 + 4);
        float4 t0 = __ldcs((const float4*)(dk + idx + h * 8));
        float4 t1 = __ldcs((const float4*)(dk + idx + h * 8 + 4));
        __half2 a = __floats2half2_rn(s0.x * t0.x, s0.y * t0.y);
        __half2 b = __floats2half2_rn(s0.z * t0.z, s0.w * t0.w);
        __half2 c = __floats2half2_rn(s1.x * t1.x, s1.y * t1.y);
        __half2 e = __floats2half2_rn(s1.z * t1.z, s1.w * t1.w);
        uint4 o;
        o.x = *(uint32_t*)&a; o.y = *(uint32_t*)&b;
        o.z = *(uint32_t*)&c; o.w = *(uint32_t*)&e;
        __stcg((uint4*)(wq + idx + h * 8), o);
    }
}

// ---------------- smem stage layout (bytes) ----------------
// A: 64 rows x 128B (K-chunk 64), row stride 144B -> 9216
// B: 64 k-rows x 256B, row stride 272B -> 17408 @9216
#define ABYT   9216
#define STAGEB 26624
#define GEMM_SMEM (STAGES * STAGEB + 512)   // ~78.5 KB -> 2 CTAs/SM

// ---------------- fp16 grouped GEMM, cp.async loader -----------------------
// Block tile 64 x 128, K-chunk 64, 3-stage cp.async pipeline, 256 threads /
// 8 warps (2M x 4N), warp tile 32 x 32. Single product D = A*W (fp32 accum).
template <int LAYER>
__global__ __launch_bounds__(256, 2)
void gemm_mma(const float* __restrict__ sb, const float* __restrict__ db,
              float* __restrict__ outp) {
    constexpr int K = (LAYER == 0) ? D0 : (LAYER == 1) ? D1 : D2;
    constexpr int N = (LAYER == 0) ? D1 : (LAYER == 1) ? D2 : D3;
    constexpr int NCH = K / 64;

    const int tyb = blockIdx.y;
    if (tyb >= g_nt64) return;
    const int d   = g_tile_d64[tyb];
    const int m0  = g_tile_m64[tyb];
    const int off = g_off[d];
    const int len = g_off[d + 1] - off;
    const int n0  = blockIdx.x * 128;
    const int gmrow0 = off + m0;

    extern __shared__ char smc[];
    float* biasS = (float*)(smc + STAGES * STAGEB);

    const int tid  = threadIdx.x;
    const int lane = tid & 31;
    const int w    = tid >> 5;
    const int mw   = w >> 2;        // 0..1 -> M offset mw*32
    const int nw   = w & 3;         // 0..3 -> N offset nw*32
    const int grp  = lane >> 2;
    const int tig  = lane & 3;

    if (tid >= 128 && tid < 160) {
        int q = tid - 128;
        float4 a = *(const float4*)(sb + n0 + q * 4);
        float4 b = *(const float4*)(db + (size_t)d * N + n0 + q * 4);
        a.x += b.x; a.y += b.y; a.z += b.z; a.w += b.w;
        *(float4*)(biasS + q * 4) = a;
    }

    const __half* Ap = (LAYER == 0) ? g_x : (LAYER == 1) ? g_h1 : g_h2;
    const __half* Wq = (LAYER == 0) ? g_w0 : (LAYER == 1) ? g_w1 : g_w2;
    __half* Cp = (LAYER == 0) ? g_h1 : g_h2;

    const uint32_t ubase = (uint32_t)__cvta_generic_to_shared(smc);

    // copy coords: 2 A segs + 4 B segs per thread
    const char* aSrc[2];
    uint32_t    aDst[2];
    const char* bSrc[4];
    uint32_t    bDst[4];
#pragma unroll
    for (int i = 0; i < 2; i++) {
        int idx  = tid + i * 256;
        int arow = idx >> 3;
        int aseg = (idx & 7) * 16;
        aSrc[i] = (const char*)(Ap + (size_t)(gmrow0 + arow) * K) + aseg;
        aDst[i] = ubase + arow * 144 + aseg;
    }
#pragma unroll
    for (int i = 0; i < 4; i++) {
        int idx  = tid + i * 256;
        int brow = idx >> 4;
        int bseg = (idx & 15) * 16;
        bSrc[i] = (const char*)(Wq + ((size_t)d * K + brow) * N + n0) + bseg;
        bDst[i] = ubase + ABYT + brow * 272 + bseg;
    }

#define COPYC(c, s)                                                           \
    {                                                                         \
        const uint32_t so  = (uint32_t)((s) * STAGEB);                        \
        const size_t   akb = (size_t)(c) * 128;          /* 64 k * 2B */      \
        const size_t   bkb = (size_t)(c) * 64 * N * 2;   /* 64 k rows */      \
        _Pragma("unroll")                                                     \
        for (int i = 0; i < 2; i++) CP16(aDst[i] + so, aSrc[i] + akb);        \
        _Pragma("unroll")                                                     \
        for (int i = 0; i < 4; i++) CP16(bDst[i] + so, bSrc[i] + bkb);        \
    }

    // prologue
    COPYC(0, 0); CP_COMMIT();
    COPYC(1, 1); CP_COMMIT();

    float acc[2][4][4];
#pragma unroll
    for (int i = 0; i < 2; i++)
#pragma unroll
        for (int j = 0; j < 4; j++)
#pragma unroll
            for (int q = 0; q < 4; q++) acc[i][j][q] = 0.f;

    // fragment read addresses
    const int Lrow = (lane & 7) + ((lane >> 3) & 1) * 8;
    const int Lk16 = (lane >> 4) & 1;
    const uint32_t aOff = ubase + (uint32_t)((mw * 32 + Lrow) * 144 + Lk16 * 16);
    const int bm = lane >> 3;
    const int bk = (bm & 1) * 8 + (lane & 7);
    const int bn = nw * 32 + (bm >> 1) * 8;
    const uint32_t bOff = ubase + ABYT + (uint32_t)(bk * 272 + bn * 2);

    for (int c = 0; c < NCH; c++) {
        const int s = c % STAGES;
        CP_WAIT1();
        __syncthreads();
        if (c + 2 < NCH) COPYC(c + 2, (c + 2) % STAGES);
        CP_COMMIT();

        const uint32_t aBs = aOff + (uint32_t)(s * STAGEB);
        const uint32_t bBs = bOff + (uint32_t)(s * STAGEB);
#pragma unroll
        for (int ks = 0; ks < 4; ks++) {
            uint32_t ah[2][4];
#pragma unroll
            for (int mt = 0; mt < 2; mt++)
                LDSM_X4(ah[mt], aBs + mt * (16 * 144) + ks * 32);
            uint32_t bq[4][2];
#pragma unroll
            for (int np = 0; np < 2; np++) {
                LDSM_X4T(bq[2 * np][0], bq[2 * np][1],
                         bq[2 * np + 1][0], bq[2 * np + 1][1],
                         bBs + ks * (16 * 272) + np * 32);
            }
#pragma unroll
            for (int nt = 0; nt < 4; nt++)
#pragma unroll
                for (int mt = 0; mt < 2; mt++)
                    MMA_F16(acc[mt][nt], ah[mt], bq[nt][0], bq[nt][1]);
        }
        __syncthreads();
    }

    // ---------------- epilogue: bias + relu + store ----------------
#pragma unroll
    for (int mt = 0; mt < 2; mt++) {
#pragma unroll
        for (int half = 0; half < 2; half++) {
            int mrow = mw * 32 + mt * 16 + grp + half * 8;
            int r = m0 + mrow;
            if (r < len) {
#pragma unroll
                for (int nt = 0; nt < 4; nt++) {
                    int col = nw * 32 + nt * 8 + 2 * tig;
                    float ox = fmaxf(acc[mt][nt][half * 2 + 0] + biasS[col], 0.f);
                    float oy = fmaxf(acc[mt][nt][half * 2 + 1] + biasS[col + 1], 0.f);
                    if (LAYER == 2) {
                        int orow = g_perm[off + r];
                        *(float2*)(outp + (size_t)orow * N + n0 + col) =
                            make_float2(ox, oy);
                    } else {
                        __half2 hv = __floats2half2_rn(ox, oy);
                        *(uint32_t*)(Cp + (size_t)(off + r) * N + n0 + col) =
                            *(uint32_t*)&hv;
                    }
                }
            }
        }
    }
}

// ---------------- launch ----------------
extern "C" void kernel_launch(void* const* d_in, const int* in_sizes, int n_in,
                              void* d_out, int out_size) {
    const float* x   = (const float*)d_in[0];
    const int*   ind = (const int*)  d_in[1];
    const float* sk0 = (const float*)d_in[2];
    const float* sb0 = (const float*)d_in[3];
    const float* dk0 = (const float*)d_in[4];
    const float* db0 = (const float*)d_in[5];
    const float* sk1 = (const float*)d_in[6];
    const float* sb1 = (const float*)d_in[7];
    const float* dk1 = (const float*)d_in[8];
    const float* db1 = (const float*)d_in[9];
    const float* sk2 = (const float*)d_in[10];
    const float* sb2 = (const float*)d_in[11];
    const float* dk2 = (const float*)d_in[12];
    const float* db2 = (const float*)d_in[13];
    float* out = (float*)d_out;

    // one-time setup (first call is the uncaptured correctness run)
    static bool init_done = false;
    static cudaStream_t sSide;
    static cudaEvent_t evFork, evJoin;
    if (!init_done) {
        cudaStreamCreateWithFlags(&sSide, cudaStreamNonBlocking);
        cudaEventCreateWithFlags(&evFork, cudaEventDisableTiming);
        cudaEventCreateWithFlags(&evJoin, cudaEventDisableTiming);
        cudaFuncSetAttribute(gemm_mma<0>, cudaFuncAttributeMaxDynamicSharedMemorySize, GEMM_SMEM);
        cudaFuncSetAttribute(gemm_mma<1>, cudaFuncAttributeMaxDynamicSharedMemorySize, GEMM_SMEM);
        cudaFuncSetAttribute(gemm_mma<2>, cudaFuncAttributeMaxDynamicSharedMemorySize, GEMM_SMEM);
        init_done = true;
    }

    // fork side stream: weight prep for layers 1 & 2 (independent of perm/x)
    cudaEventRecord(evFork, 0);
    cudaStreamWaitEvent(sSide, evFork, 0);
    prep_w<1><<<(NDOM * D1 * D2 / 16 + 255) / 256, 256, 0, sSide>>>(sk1, dk1);
    prep_w<2><<<(NDOM * D2 * D3 / 16 + 255) / 256, 256, 0, sSide>>>(sk2, dk2);
    cudaEventRecord(evJoin, sSide);

    // main stream: layer-0 critical path
    build_perm<<<1, 1024>>>(ind);
    prep_x<<<(B_ROWS * D0 / 8 + 255) / 256, 256>>>(x);
    prep_w<0><<<(NDOM * D0 * D1 / 16 + 255) / 256, 256>>>(sk0, dk0);

    gemm_mma<0><<<dim3(D1 / 128, MAXT64), 256, GEMM_SMEM>>>(sb0, db0, nullptr);
    cudaStreamWaitEvent(0, evJoin, 0);
    gemm_mma<1><<<dim3(D2 / 128, MAXT64), 256, GEMM_SMEM>>>(sb1, db1, nullptr);
    gemm_mma<2><<<dim3(D3 / 128, MAXT64), 256, GEMM_SMEM>>>(sb2, db2, out);
}

// round 17
// speedup vs baseline: 2.2570x; 1.0309x over previous
#include <cuda_runtime.h>
#include <cuda_fp16.h>
#include <cstdint>

// Problem constants
#define B_ROWS 4096
#define NDOM 8
#define D0 1024
#define D1 1024
#define D2 512
#define D3 256
#define MAXT64 72
#define MTILE 64
#define PADR 64
#define STAGES 3

// ---------------- device scratch ----------------
__device__ int   g_perm[B_ROWS];
__device__ int   g_off[NDOM + 1];
__device__ int   g_tile_d64[MAXT64];
__device__ int   g_tile_m64[MAXT64];
__device__ int   g_nt64;
// fp16 planes: x in ORIGINAL order; h1/h2 in sorted order; weights [d][k][n]
__device__ __half g_x [(B_ROWS + PADR) * D0];
__device__ __half g_h1[(B_ROWS + PADR) * D1];
__device__ __half g_h2[(B_ROWS + PADR) * D2];
__device__ __half g_w0[NDOM * D0 * D1];
__device__ __half g_w1[NDOM * D1 * D2];
__device__ __half g_w2[NDOM * D2 * D3];

#define MMA_F16(d, a, b0, b1)                                                 \
    asm volatile(                                                             \
        "mma.sync.aligned.m16n8k16.row.col.f32.f16.f16.f32 "                  \
        "{%0,%1,%2,%3}, {%4,%5,%6,%7}, {%8,%9}, {%0,%1,%2,%3};"               \
        : "+f"((d)[0]), "+f"((d)[1]), "+f"((d)[2]), "+f"((d)[3])              \
        : "r"((a)[0]), "r"((a)[1]), "r"((a)[2]), "r"((a)[3]),                 \
          "r"(b0), "r"(b1))

#define LDSM_X4(r, addr)                                                      \
    asm volatile("ldmatrix.sync.aligned.m8n8.x4.shared.b16 "                  \
                 "{%0,%1,%2,%3}, [%4];"                                       \
                 : "=r"((r)[0]), "=r"((r)[1]), "=r"((r)[2]), "=r"((r)[3])     \
                 : "r"(addr))

#define LDSM_X4T(r0, r1, r2, r3, addr)                                        \
    asm volatile("ldmatrix.sync.aligned.m8n8.x4.trans.shared.b16 "            \
                 "{%0,%1,%2,%3}, [%4];"                                       \
                 : "=r"(r0), "=r"(r1), "=r"(r2), "=r"(r3)                     \
                 : "r"(addr))

#define CP16(dst, src)                                                        \
    asm volatile("cp.async.cg.shared.global [%0], [%1], 16;"                  \
                 :: "r"(dst), "l"(src))
#define CP_COMMIT() asm volatile("cp.async.commit_group;" ::: "memory")
#define CP_WAIT1()  asm volatile("cp.async.wait_group 1;" ::: "memory")

// ---------------- permutation + tile list ----------------
__global__ void build_perm(const int* __restrict__ ind) {
    __shared__ int cnt[NDOM];
    __shared__ int cur[NDOM];
    int t = threadIdx.x;
    if (t < NDOM) cnt[t] = 0;
    __syncthreads();
    for (int i = t; i < B_ROWS; i += blockDim.x) atomicAdd(&cnt[ind[i]], 1);
    __syncthreads();
    if (t == 0) {
        int s = 0;
        for (int d = 0; d < NDOM; d++) { g_off[d] = s; cur[d] = s; s += cnt[d]; }
        g_off[NDOM] = s;
        int n64 = 0;
        for (int d = 0; d < NDOM; d++) {
            int len = g_off[d + 1] - g_off[d];
            for (int m0 = 0; m0 < len; m0 += MTILE) {
                g_tile_d64[n64] = d; g_tile_m64[n64] = m0; n64++;
            }
        }
        g_nt64 = n64;
    }
    __syncthreads();
    for (int i = t; i < B_ROWS; i += blockDim.x) {
        int d = ind[i];
        int p = atomicAdd(&cur[d], 1);
        g_perm[p] = i;
    }
}

// ---------------- prepass: convert x -> fp16 (ORIGINAL order, no perm) -----
__global__ void prep_x(const float* __restrict__ x) {
    int i = blockIdx.x * 256 + threadIdx.x;
    if (i >= B_ROWS * D0 / 8) return;
    size_t e = (size_t)i * 8;
    const float4* src = (const float4*)(x + e);
    float4 v0 = __ldcs(src);
    float4 v1 = __ldcs(src + 1);
    __half2 a = __floats2half2_rn(v0.x, v0.y);
    __half2 b = __floats2half2_rn(v0.z, v0.w);
    __half2 c = __floats2half2_rn(v1.x, v1.y);
    __half2 e2 = __floats2half2_rn(v1.z, v1.w);
    uint4 o;
    o.x = *(uint32_t*)&a; o.y = *(uint32_t*)&b;
    o.z = *(uint32_t*)&c; o.w = *(uint32_t*)&e2;
    __stcg((uint4*)(g_x + e), o);
}

// ---------------- prepass: fuse sk*dk -> single fp16 plane ----------------
template <int LAYER>
__global__ void prep_w(const float* __restrict__ sk, const float* __restrict__ dk) {
    constexpr int K = (LAYER == 0) ? D0 : (LAYER == 1) ? D1 : D2;
    constexpr int N = (LAYER == 0) ? D1 : (LAYER == 1) ? D2 : D3;
    __half* wq = (LAYER == 0) ? g_w0 : (LAYER == 1) ? g_w1 : g_w2;
    int i = blockIdx.x * 256 + threadIdx.x;
    if (i >= NDOM * K * N / 16) return;
    size_t idx = (size_t)i * 16;
    size_t kn  = idx % (K * N);
#pragma unroll
    for (int h = 0; h < 2; h++) {
        float4 s0 = *(const float4*)(sk + kn + h * 8);
        float4 s1 = *(const float4*)(sk + kn + h * 8 + 4);
        float4 t0 = __ldcs((const float4*)(dk + idx + h * 8));
        float4 t1 = __ldcs((const float4*)(dk + idx + h * 8 + 4));
        __half2 a = __floats2half2_rn(s0.x * t0.x, s0.y * t0.y);
        __half2 b = __floats2half2_rn(s0.z * t0.z, s0.w * t0.w);
        __half2 c = __floats2half2_rn(s1.x * t1.x, s1.y * t1.y);
        __half2 e = __floats2half2_rn(s1.z * t1.z, s1.w * t1.w);
        uint4 o;
        o.x = *(uint32_t*)&a; o.y = *(uint32_t*)&b;
        o.z = *(uint32_t*)&c; o.w = *(uint32_t*)&e;
        __stcg((uint4*)(wq + idx + h * 8), o);
    }
}

// ---------------- smem stage layout (bytes) ----------------
// A: 64 rows x 128B (K-chunk 64), row stride 144B -> 9216
// B: 64 k-rows x 256B, row stride 272B -> 17408 @9216
#define ABYT   9216
#define STAGEB 26624
#define SM_RI  (STAGES * STAGEB)            // rowIdx int[64] (layer 0)
#define SM_BI  (SM_RI + 256)
#define GEMM_SMEM (SM_BI + 512)             // ~79 KB -> 2 CTAs/SM

// ---------------- fp16 grouped GEMM, cp.async loader -----------------------
// Block tile 64 x 128, K-chunk 64, 3-stage cp.async pipeline, 256 threads /
// 8 warps (2M x 4N), warp tile 32 x 32. Layer 0 gathers A rows via g_perm.
template <int LAYER>
__global__ __launch_bounds__(256, 2)
void gemm_mma(const float* __restrict__ sb, const float* __restrict__ db,
              float* __restrict__ outp) {
    constexpr int K = (LAYER == 0) ? D0 : (LAYER == 1) ? D1 : D2;
    constexpr int N = (LAYER == 0) ? D1 : (LAYER == 1) ? D2 : D3;
    constexpr int NCH = K / 64;

    const int tyb = blockIdx.y;
    if (tyb >= g_nt64) return;
    const int d   = g_tile_d64[tyb];
    const int m0  = g_tile_m64[tyb];
    const int off = g_off[d];
    const int len = g_off[d + 1] - off;
    const int n0  = blockIdx.x * 128;
    const int gmrow0 = off + m0;

    extern __shared__ char smc[];
    int*   rowIdx = (int*)(smc + SM_RI);
    float* biasS  = (float*)(smc + SM_BI);

    const int tid  = threadIdx.x;
    const int lane = tid & 31;
    const int w    = tid >> 5;
    const int mw   = w >> 2;        // 0..1 -> M offset mw*32
    const int nw   = w & 3;         // 0..3 -> N offset nw*32
    const int grp  = lane >> 2;
    const int tig  = lane & 3;

    if (LAYER == 0 && tid < MTILE) {
        int r = m0 + tid;
        rowIdx[tid] = (r < len) ? g_perm[off + r] : 0;
    }
    if (tid >= 128 && tid < 160) {
        int q = tid - 128;
        float4 a = *(const float4*)(sb + n0 + q * 4);
        float4 b = *(const float4*)(db + (size_t)d * N + n0 + q * 4);
        a.x += b.x; a.y += b.y; a.z += b.z; a.w += b.w;
        *(float4*)(biasS + q * 4) = a;
    }
    __syncthreads();

    const __half* Ap = (LAYER == 0) ? g_x : (LAYER == 1) ? g_h1 : g_h2;
    const __half* Wq = (LAYER == 0) ? g_w0 : (LAYER == 1) ? g_w1 : g_w2;
    __half* Cp = (LAYER == 0) ? g_h1 : g_h2;

    const uint32_t ubase = (uint32_t)__cvta_generic_to_shared(smc);

    // copy coords: 2 A segs + 4 B segs per thread
    const char* aSrc[2];
    uint32_t    aDst[2];
    const char* bSrc[4];
    uint32_t    bDst[4];
#pragma unroll
    for (int i = 0; i < 2; i++) {
        int idx  = tid + i * 256;
        int arow = idx >> 3;
        int aseg = (idx & 7) * 16;
        int srow = (LAYER == 0) ? rowIdx[arow] : (gmrow0 + arow);
        aSrc[i] = (const char*)(Ap + (size_t)srow * K) + aseg;
        aDst[i] = ubase + arow * 144 + aseg;
    }
#pragma unroll
    for (int i = 0; i < 4; i++) {
        int idx  = tid + i * 256;
        int brow = idx >> 4;
        int bseg = (idx & 15) * 16;
        bSrc[i] = (const char*)(Wq + ((size_t)d * K + brow) * N + n0) + bseg;
        bDst[i] = ubase + ABYT + brow * 272 + bseg;
    }

#define COPYC(c, s)                                                           \
    {                                                                         \
        const uint32_t so  = (uint32_t)((s) * STAGEB);                        \
        const size_t   akb = (size_t)(c) * 128;          /* 64 k * 2B */      \
        const size_t   bkb = (size_t)(c) * 64 * N * 2;   /* 64 k rows */      \
        _Pragma("unroll")                                                     \
        for (int i = 0; i < 2; i++) CP16(aDst[i] + so, aSrc[i] + akb);        \
        _Pragma("unroll")                                                     \
        for (int i = 0; i < 4; i++) CP16(bDst[i] + so, bSrc[i] + bkb);        \
    }

    // prologue
    COPYC(0, 0); CP_COMMIT();
    COPYC(1, 1); CP_COMMIT();

    float acc[2][4][4];
#pragma unroll
    for (int i = 0; i < 2; i++)
#pragma unroll
        for (int j = 0; j < 4; j++)
#pragma unroll
            for (int q = 0; q < 4; q++) acc[i][j][q] = 0.f;

    // fragment read addresses
    const int Lrow = (lane & 7) + ((lane >> 3) & 1) * 8;
    const int Lk16 = (lane >> 4) & 1;
    const uint32_t aOff = ubase + (uint32_t)((mw * 32 + Lrow) * 144 + Lk16 * 16);
    const int bm = lane >> 3;
    const int bk = (bm & 1) * 8 + (lane & 7);
    const int bn = nw * 32 + (bm >> 1) * 8;
    const uint32_t bOff = ubase + ABYT + (uint32_t)(bk * 272 + bn * 2);

    for (int c = 0; c < NCH; c++) {
        const int s = c % STAGES;
        CP_WAIT1();
        __syncthreads();
        if (c + 2 < NCH) COPYC(c + 2, (c + 2) % STAGES);
        CP_COMMIT();

        const uint32_t aBs = aOff + (uint32_t)(s * STAGEB);
        const uint32_t bBs = bOff + (uint32_t)(s * STAGEB);
#pragma unroll
        for (int ks = 0; ks < 4; ks++) {
            uint32_t ah[2][4];
#pragma unroll
            for (int mt = 0; mt < 2; mt++)
                LDSM_X4(ah[mt], aBs + mt * (16 * 144) + ks * 32);
            uint32_t bq[4][2];
#pragma unroll
            for (int np = 0; np < 2; np++) {
                LDSM_X4T(bq[2 * np][0], bq[2 * np][1],
                         bq[2 * np + 1][0], bq[2 * np + 1][1],
                         bBs + ks * (16 * 272) + np * 32);
            }
#pragma unroll
            for (int nt = 0; nt < 4; nt++)
#pragma unroll
                for (int mt = 0; mt < 2; mt++)
                    MMA_F16(acc[mt][nt], ah[mt], bq[nt][0], bq[nt][1]);
        }
        __syncthreads();
    }

    // ---------------- epilogue: bias + relu + store ----------------
#pragma unroll
    for (int mt = 0; mt < 2; mt++) {
#pragma unroll
        for (int half = 0; half < 2; half++) {
            int mrow = mw * 32 + mt * 16 + grp + half * 8;
            int r = m0 + mrow;
            if (r < len) {
#pragma unroll
                for (int nt = 0; nt < 4; nt++) {
                    int col = nw * 32 + nt * 8 + 2 * tig;
                    float ox = fmaxf(acc[mt][nt][half * 2 + 0] + biasS[col], 0.f);
                    float oy = fmaxf(acc[mt][nt][half * 2 + 1] + biasS[col + 1], 0.f);
                    if (LAYER == 2) {
                        int orow = g_perm[off + r];
                        *(float2*)(outp + (size_t)orow * N + n0 + col) =
                            make_float2(ox, oy);
                    } else {
                        __half2 hv = __floats2half2_rn(ox, oy);
                        *(uint32_t*)(Cp + (size_t)(off + r) * N + n0 + col) =
                            *(uint32_t*)&hv;
                    }
                }
            }
        }
    }
}

// ---------------- launch ----------------
extern "C" void kernel_launch(void* const* d_in, const int* in_sizes, int n_in,
                              void* d_out, int out_size) {
    const float* x   = (const float*)d_in[0];
    const int*   ind = (const int*)  d_in[1];
    const float* sk0 = (const float*)d_in[2];
    const float* sb0 = (const float*)d_in[3];
    const float* dk0 = (const float*)d_in[4];
    const float* db0 = (const float*)d_in[5];
    const float* sk1 = (const float*)d_in[6];
    const float* sb1 = (const float*)d_in[7];
    const float* dk1 = (const float*)d_in[8];
    const float* db1 = (const float*)d_in[9];
    const float* sk2 = (const float*)d_in[10];
    const float* sb2 = (const float*)d_in[11];
    const float* dk2 = (const float*)d_in[12];
    const float* db2 = (const float*)d_in[13];
    float* out = (float*)d_out;

    // one-time setup (first call is the uncaptured correctness run)
    static bool init_done = false;
    static cudaStream_t s1, s2;
    static cudaEvent_t evFork, evX, evW0, evW2;
    if (!init_done) {
        cudaStreamCreateWithFlags(&s1, cudaStreamNonBlocking);
        cudaStreamCreateWithFlags(&s2, cudaStreamNonBlocking);
        cudaEventCreateWithFlags(&evFork, cudaEventDisableTiming);
        cudaEventCreateWithFlags(&evX,    cudaEventDisableTiming);
        cudaEventCreateWithFlags(&evW0,   cudaEventDisableTiming);
        cudaEventCreateWithFlags(&evW2,   cudaEventDisableTiming);
        cudaFuncSetAttribute(gemm_mma<0>, cudaFuncAttributeMaxDynamicSharedMemorySize, GEMM_SMEM);
        cudaFuncSetAttribute(gemm_mma<1>, cudaFuncAttributeMaxDynamicSharedMemorySize, GEMM_SMEM);
        cudaFuncSetAttribute(gemm_mma<2>, cudaFuncAttributeMaxDynamicSharedMemorySize, GEMM_SMEM);
        init_done = true;
    }

    // fork: s1 converts x; s2 converts weights (w0 first - on critical path)
    cudaEventRecord(evFork, 0);
    cudaStreamWaitEvent(s1, evFork, 0);
    cudaStreamWaitEvent(s2, evFork, 0);
    prep_x<<<(B_ROWS * D0 / 8 + 255) / 256, 256, 0, s1>>>(x);
    cudaEventRecord(evX, s1);
    prep_w<0><<<(NDOM * D0 * D1 / 16 + 255) / 256, 256, 0, s2>>>(sk0, dk0);
    cudaEventRecord(evW0, s2);
    prep_w<1><<<(NDOM * D1 * D2 / 16 + 255) / 256, 256, 0, s2>>>(sk1, dk1);
    prep_w<2><<<(NDOM * D2 * D3 / 16 + 255) / 256, 256, 0, s2>>>(sk2, dk2);
    cudaEventRecord(evW2, s2);

    // main: perm (concurrent with preps), then gemm chain
    build_perm<<<1, 1024>>>(ind);
    cudaStreamWaitEvent(0, evX, 0);
    cudaStreamWaitEvent(0, evW0, 0);
    gemm_mma<0><<<dim3(D1 / 128, MAXT64), 256, GEMM_SMEM>>>(sb0, db0, nullptr);
    cudaStreamWaitEvent(0, evW2, 0);
    gemm_mma<1><<<dim3(D2 / 128, MAXT64), 256, GEMM_SMEM>>>(sb1, db1, nullptr);
    gemm_mma<2><<<dim3(D3 / 128, MAXT64), 256, GEMM_SMEM>>>(sb2, db2, out);
}